// round 2
// baseline (speedup 1.0000x reference)
#include <cuda_runtime.h>
#include <math.h>

#define BB 4
#define CC 64
#define FF 256
#define TT 400
#define DC 16
#define SP (FF*TT)

typedef unsigned long long ull;

__device__ __forceinline__ ull pack2(float lo, float hi) {
    ull r; asm("mov.b64 %0, {%1, %2};" : "=l"(r) : "f"(lo), "f"(hi)); return r;
}
__device__ __forceinline__ void unpack2(ull p, float& lo, float& hi) {
    asm("mov.b64 {%0, %1}, %2;" : "=f"(lo), "=f"(hi) : "l"(p));
}
__device__ __forceinline__ ull ffma2(ull a, ull b, ull c) {
    ull d; asm("fma.rn.f32x2 %0, %1, %2, %3;" : "=l"(d) : "l"(a), "l"(b), "l"(c)); return d;
}
__device__ __forceinline__ ull mul2(ull a, ull b) {
    ull d; asm("mul.rn.f32x2 %0, %1, %2;" : "=l"(d) : "l"(a), "l"(b)); return d;
}
__device__ __forceinline__ float ex2f(float x) {
    float r; asm("ex2.approx.ftz.f32 %0, %1;" : "=f"(r) : "f"(x)); return r;
}

#define QS 0.36067376022224085f   /* 0.25 * log2(e) */

// ---------------- scratch ----------------
static __device__ float g_qkvf_t[(size_t)BB*48*FF*TT];  // [b][oc48][f][t]
static __device__ float g_qkvf_f[(size_t)BB*TT*48*FF];  // [b][t][oc48][f]
static __device__ float g_tqk  [(size_t)BB*FF*32*TT];   // [b][f][oc32][t]
static __device__ float g_fout_t[(size_t)BB*TT*DC*FF];  // [b][t][c][f]
static __device__ float g_fout_f[(size_t)BB*FF*DC*TT];  // [b][f][c][t]

// ---------------- kernel 1: fused conv1x1 (fqkv|tqk) + BN + PReLU ----------------
// weights stored transposed in smem: wsm[c*80 + oc], so oc-pairs are contiguous
__global__ __launch_bounds__(256)
void asa_conv_qkv_kernel(const float* __restrict__ inp,
    const float* __restrict__ w_fqkv, const float* __restrict__ w_tqk,
    const float* __restrict__ g1, const float* __restrict__ b1,
    const float* __restrict__ m1, const float* __restrict__ v1, const float* __restrict__ a1,
    const float* __restrict__ g2, const float* __restrict__ b2,
    const float* __restrict__ m2, const float* __restrict__ v2, const float* __restrict__ a2)
{
    __shared__ float wsm[64*80];
    __shared__ float scs[80], shs[80], als[80];
    int b = blockIdx.y;
    int tid = threadIdx.x;
    for (int i = tid; i < 3072; i += 256) { int oc = i >> 6, c = i & 63; wsm[c*80 + oc] = w_fqkv[i]; }
    for (int i = tid; i < 2048; i += 256) { int oc = (i >> 6) + 48, c = i & 63; wsm[c*80 + oc] = w_tqk[i]; }
    if (tid < 80) {
        float g, bi, mi, vi, ai;
        if (tid < 48) { g = g1[tid]; bi = b1[tid]; mi = m1[tid]; vi = v1[tid]; ai = a1[tid]; }
        else { int j = tid - 48; g = g2[j]; bi = b2[j]; mi = m2[j]; vi = v2[j]; ai = a2[j]; }
        float s = g * rsqrtf(vi + 1e-5f);
        scs[tid] = s; shs[tid] = bi - mi * s; als[tid] = ai;
    }
    __syncthreads();
    if (tid >= 200) return;
    int f = blockIdx.x * 2 + (tid >= 100);
    int t4 = (tid % 100) * 4;
    size_t base = (((size_t)b * CC) * FF + f) * TT + t4;

    for (int oc0 = 0; oc0 < 80; oc0 += 16) {
        ull acc[8][4];   // [oc-pair][x,y,z,w]
        #pragma unroll
        for (int jp = 0; jp < 8; jp++) {
            acc[jp][0] = 0ULL; acc[jp][1] = 0ULL; acc[jp][2] = 0ULL; acc[jp][3] = 0ULL;
        }
        #pragma unroll 2
        for (int c = 0; c < 64; c++) {
            float4 iv = *(const float4*)(inp + base + (size_t)c * SP);
            ull px = pack2(iv.x, iv.x), py = pack2(iv.y, iv.y);
            ull pz = pack2(iv.z, iv.z), pw = pack2(iv.w, iv.w);
            const ulonglong2* wr = (const ulonglong2*)(wsm + c * 80 + oc0);
            #pragma unroll
            for (int k = 0; k < 4; k++) {
                ulonglong2 w2 = wr[k];
                acc[2*k  ][0] = ffma2(w2.x, px, acc[2*k  ][0]);
                acc[2*k  ][1] = ffma2(w2.x, py, acc[2*k  ][1]);
                acc[2*k  ][2] = ffma2(w2.x, pz, acc[2*k  ][2]);
                acc[2*k  ][3] = ffma2(w2.x, pw, acc[2*k  ][3]);
                acc[2*k+1][0] = ffma2(w2.y, px, acc[2*k+1][0]);
                acc[2*k+1][1] = ffma2(w2.y, py, acc[2*k+1][1]);
                acc[2*k+1][2] = ffma2(w2.y, pz, acc[2*k+1][2]);
                acc[2*k+1][3] = ffma2(w2.y, pw, acc[2*k+1][3]);
            }
        }
        #pragma unroll
        for (int jp = 0; jp < 8; jp++) {
            float lx0, lx1, ly0, ly1, lz0, lz1, lw0, lw1;
            unpack2(acc[jp][0], lx0, lx1);
            unpack2(acc[jp][1], ly0, ly1);
            unpack2(acc[jp][2], lz0, lz1);
            unpack2(acc[jp][3], lw0, lw1);
            #pragma unroll
            for (int h = 0; h < 2; h++) {
                int oc = oc0 + 2*jp + h;
                float s = scs[oc], sh = shs[oc], al = als[oc];
                float4 r;
                r.x = fmaf(h ? lx1 : lx0, s, sh);
                r.y = fmaf(h ? ly1 : ly0, s, sh);
                r.z = fmaf(h ? lz1 : lz0, s, sh);
                r.w = fmaf(h ? lw1 : lw0, s, sh);
                r.x = r.x > 0.f ? r.x : al * r.x;
                r.y = r.y > 0.f ? r.y : al * r.y;
                r.z = r.z > 0.f ? r.z : al * r.z;
                r.w = r.w > 0.f ? r.w : al * r.w;
                if (oc < 48) {
                    *(float4*)&g_qkvf_t[(((size_t)b * 48 + oc) * FF + f) * TT + t4] = r;
                } else {
                    *(float4*)&g_tqk[(((size_t)b * FF + f) * 32 + (oc - 48)) * TT + t4] = r;
                }
            }
        }
    }
}

// ---------------- transpose 1: [b][oc][f][t] -> [b][t][oc][f] ----------------
__global__ __launch_bounds__(256)
void asa_transpose_qkv_kernel()
{
    __shared__ float tile[32][33];
    int z = blockIdx.z;
    int t0 = blockIdx.x * 32, f0 = blockIdx.y * 32;
    int tx = threadIdx.x, ty = threadIdx.y;
    size_t ibase = (size_t)z * FF * TT;
    #pragma unroll
    for (int k = 0; k < 32; k += 8) {
        int t = t0 + tx, f = f0 + ty + k;
        if (t < TT) tile[ty + k][tx] = g_qkvf_t[ibase + (size_t)f * TT + t];
    }
    __syncthreads();
    int b = z / 48, oc = z % 48;
    #pragma unroll
    for (int k = 0; k < 32; k += 8) {
        int t = t0 + ty + k, f = f0 + tx;
        if (t < TT) g_qkvf_f[((size_t)(b * TT + t) * 48 + oc) * FF + f] = tile[tx][ty + k];
    }
}

// ---------------- kernel 2: frequency attention ----------------
__global__ __launch_bounds__(256)
void asa_freq_attn_kernel()
{
    __shared__ float ks[16 * 256];
    __shared__ float vs[16 * 256];
    int t = blockIdx.x, b = blockIdx.y;
    int f = threadIdx.x;
    const float* base = g_qkvf_f + (size_t)(b * TT + t) * 48 * FF;
    for (int i = f; i < 1024; i += 256) {
        ((float4*)ks)[i] = ((const float4*)(base + 4096))[i];
        ((float4*)vs)[i] = ((const float4*)(base + 8192))[i];
    }
    __syncthreads();

    ull qq[16];
    #pragma unroll
    for (int c = 0; c < 16; c++) { float qv = base[c * 256 + f] * QS; qq[c] = pack2(qv, qv); }

    float mx = -3e38f, l = 0.f;
    ull acc2[16];
    #pragma unroll
    for (int c = 0; c < 16; c++) acc2[c] = 0ULL;

    for (int y0 = 0; y0 < 256; y0 += 32) {
        ull s2[16];
        #pragma unroll
        for (int j = 0; j < 16; j++) s2[j] = 0ULL;
        #pragma unroll 4
        for (int c = 0; c < 16; c++) {
            const ulonglong2* kp = (const ulonglong2*)(ks + c * 256 + y0);
            ull qc = qq[c];
            #pragma unroll
            for (int j = 0; j < 8; j++) {
                ulonglong2 kk = kp[j];
                s2[2*j]   = ffma2(qc, kk.x, s2[2*j]);
                s2[2*j+1] = ffma2(qc, kk.y, s2[2*j+1]);
            }
        }
        float cm = -3e38f;
        #pragma unroll
        for (int j = 0; j < 16; j++) {
            float lo, hi; unpack2(s2[j], lo, hi);
            cm = fmaxf(cm, fmaxf(lo, hi));
        }
        float nm = fmaxf(mx, cm);
        float corr = ex2f(mx - nm);
        l *= corr;
        ull pc = pack2(corr, corr);
        #pragma unroll
        for (int c = 0; c < 16; c++) acc2[c] = mul2(acc2[c], pc);
        float ps = 0.f;
        #pragma unroll
        for (int j = 0; j < 16; j++) {
            float lo, hi; unpack2(s2[j], lo, hi);
            lo = ex2f(lo - nm); hi = ex2f(hi - nm);
            ps += lo + hi;
            s2[j] = pack2(lo, hi);
        }
        l += ps;
        #pragma unroll 4
        for (int c = 0; c < 16; c++) {
            const ulonglong2* vp = (const ulonglong2*)(vs + c * 256 + y0);
            ull a = acc2[c];
            #pragma unroll
            for (int j = 0; j < 8; j++) {
                ulonglong2 vv = vp[j];
                a = ffma2(s2[2*j], vv.x, a);
                a = ffma2(s2[2*j+1], vv.y, a);
            }
            acc2[c] = a;
        }
        mx = nm;
    }
    float inv = 1.f / l;
    size_t ob = (size_t)(b * TT + t) * DC * FF + f;
    #pragma unroll
    for (int c = 0; c < 16; c++) {
        float lo, hi; unpack2(acc2[c], lo, hi);
        g_fout_t[ob + c * 256] = (lo + hi) * inv;
    }
}

// ---------------- transpose 2: [b][t][c][f] -> [b][f][c][t] ----------------
__global__ __launch_bounds__(256)
void asa_transpose_fout_kernel()
{
    __shared__ float tile[32][33];
    int z = blockIdx.z;
    int f0 = blockIdx.x * 32, t0 = blockIdx.y * 32;
    int tx = threadIdx.x, ty = threadIdx.y;
    int b = z / 16, c = z % 16;
    #pragma unroll
    for (int k = 0; k < 32; k += 8) {
        int t = t0 + ty + k, f = f0 + tx;
        if (t < TT) tile[ty + k][tx] = g_fout_t[((size_t)(b * TT + t) * DC + c) * FF + f];
    }
    __syncthreads();
    #pragma unroll
    for (int k = 0; k < 32; k += 8) {
        int f = f0 + ty + k, t = t0 + tx;
        if (t < TT) g_fout_f[((size_t)(b * FF + f) * DC + c) * TT + t] = tile[tx][ty + k];
    }
}

// ---- kernel 3: causal time attention + proj conv + BN + PReLU + residual ----
__global__ __launch_bounds__(416)
void asa_time_attn_kernel(const float* __restrict__ inp, const float* __restrict__ w_proj,
    const float* __restrict__ g3, const float* __restrict__ b3, const float* __restrict__ m3,
    const float* __restrict__ v3, const float* __restrict__ a3, float* __restrict__ out)
{
    extern __shared__ float sm[];
    float* kt  = sm;            // 16*400
    float* vf  = sm + 6400;     // 16*400
    float* wp  = sm + 12800;    // 64*16
    float* sc3 = sm + 13824;
    float* sh3 = sm + 13888;
    float* al3 = sm + 13952;

    int f = blockIdx.x, b = blockIdx.y;
    int tid = threadIdx.x;
    size_t tbase = (size_t)(b * FF + f) * 32 * TT;
    size_t fbase = (size_t)(b * FF + f) * DC * TT;
    for (int i = tid; i < 1600; i += 416) {
        ((float4*)kt)[i] = ((const float4*)(g_tqk + tbase + 6400))[i];
        ((float4*)vf)[i] = ((const float4*)(g_fout_f + fbase))[i];
    }
    for (int i = tid; i < 1024; i += 416) wp[i] = w_proj[i];
    if (tid < 64) {
        float s = g3[tid] * rsqrtf(v3[tid] + 1e-5f);
        sc3[tid] = s; sh3[tid] = b3[tid] - m3[tid] * s; al3[tid] = a3[tid];
    }
    __syncthreads();
    if (tid >= TT) return;
    int t = tid;

    ull qq[16];
    #pragma unroll
    for (int c = 0; c < 16; c++) { float qv = g_tqk[tbase + c * TT + t] * QS; qq[c] = pack2(qv, qv); }

    float mx = -3e38f, l = 0.f;
    ull acc2[16];
    #pragma unroll
    for (int c = 0; c < 16; c++) acc2[c] = 0ULL;

    int nch = (t >> 5) + 1;
    for (int ch = 0; ch < nch; ch++) {
        int y0 = ch * 32;
        ull s2[16];
        #pragma unroll
        for (int j = 0; j < 16; j++) s2[j] = 0ULL;
        #pragma unroll 4
        for (int c = 0; c < 16; c++) {
            const ulonglong2* kp = (const ulonglong2*)(kt + c * TT + y0);
            ull qc = qq[c];
            #pragma unroll
            for (int j = 0; j < 8; j++) {
                ulonglong2 kk = kp[j];
                s2[2*j]   = ffma2(qc, kk.x, s2[2*j]);
                s2[2*j+1] = ffma2(qc, kk.y, s2[2*j+1]);
            }
        }
        if (y0 + 31 > t) {
            #pragma unroll
            for (int j = 0; j < 16; j++) {
                float lo, hi; unpack2(s2[j], lo, hi);
                int y = y0 + 2*j;
                if (y   > t) lo = -3e38f;
                if (y+1 > t) hi = -3e38f;
                s2[j] = pack2(lo, hi);
            }
        }
        float cm = -3e38f;
        #pragma unroll
        for (int j = 0; j < 16; j++) {
            float lo, hi; unpack2(s2[j], lo, hi);
            cm = fmaxf(cm, fmaxf(lo, hi));
        }
        float nm = fmaxf(mx, cm);
        float corr = ex2f(mx - nm);
        l *= corr;
        ull pc = pack2(corr, corr);
        #pragma unroll
        for (int c = 0; c < 16; c++) acc2[c] = mul2(acc2[c], pc);
        float ps = 0.f;
        #pragma unroll
        for (int j = 0; j < 16; j++) {
            float lo, hi; unpack2(s2[j], lo, hi);
            lo = ex2f(lo - nm); hi = ex2f(hi - nm);
            ps += lo + hi;
            s2[j] = pack2(lo, hi);
        }
        l += ps;
        #pragma unroll 4
        for (int c = 0; c < 16; c++) {
            const ulonglong2* vp = (const ulonglong2*)(vf + c * TT + y0);
            ull a = acc2[c];
            #pragma unroll
            for (int j = 0; j < 8; j++) {
                ulonglong2 vv = vp[j];
                a = ffma2(s2[2*j], vv.x, a);
                a = ffma2(s2[2*j+1], vv.y, a);
            }
            acc2[c] = a;
        }
        mx = nm;
    }
    float inv = 1.f / l;
    ull pa[8];
    #pragma unroll
    for (int jp = 0; jp < 8; jp++) {
        float lo0, hi0, lo1, hi1;
        unpack2(acc2[2*jp],   lo0, hi0);
        unpack2(acc2[2*jp+1], lo1, hi1);
        pa[jp] = pack2((lo0 + hi0) * inv, (lo1 + hi1) * inv);
    }

    size_t obase = (((size_t)b * CC) * FF + f) * TT + t;
    #pragma unroll 8
    for (int oc = 0; oc < CC; oc++) {
        const ulonglong2* wr = (const ulonglong2*)(wp + oc * 16);
        ull r2 = 0ULL;
        #pragma unroll
        for (int k = 0; k < 4; k++) {
            ulonglong2 w2 = wr[k];
            r2 = ffma2(pa[2*k],   w2.x, r2);
            r2 = ffma2(pa[2*k+1], w2.y, r2);
        }
        float lo, hi; unpack2(r2, lo, hi);
        float r = lo + hi;
        r = fmaf(r, sc3[oc], sh3[oc]);
        r = r > 0.f ? r : al3[oc] * r;
        out[obase + (size_t)oc * SP] = r + inp[obase + (size_t)oc * SP];
    }
}

// ---------------- launcher ----------------
extern "C" void kernel_launch(void* const* d_in, const int* in_sizes, int n_in,
                              void* d_out, int out_size)
{
    (void)in_sizes; (void)n_in; (void)out_size;
    const float* inp    = (const float*)d_in[0];
    const float* w_fqkv = (const float*)d_in[2];
    const float* g1 = (const float*)d_in[3];
    const float* b1 = (const float*)d_in[4];
    const float* m1 = (const float*)d_in[5];
    const float* v1 = (const float*)d_in[6];
    const float* a1 = (const float*)d_in[7];
    const float* w_tqk  = (const float*)d_in[8];
    const float* g2 = (const float*)d_in[9];
    const float* b2 = (const float*)d_in[10];
    const float* m2 = (const float*)d_in[11];
    const float* v2 = (const float*)d_in[12];
    const float* a2 = (const float*)d_in[13];
    const float* w_proj = (const float*)d_in[14];
    const float* g3 = (const float*)d_in[15];
    const float* b3 = (const float*)d_in[16];
    const float* m3 = (const float*)d_in[17];
    const float* v3 = (const float*)d_in[18];
    const float* a3 = (const float*)d_in[19];
    float* out = (float*)d_out;

    cudaFuncSetAttribute(asa_time_attn_kernel,
                         cudaFuncAttributeMaxDynamicSharedMemorySize, 14016 * 4);

    asa_conv_qkv_kernel<<<dim3(FF/2, BB), 256>>>(inp, w_fqkv, w_tqk,
        g1, b1, m1, v1, a1, g2, b2, m2, v2, a2);
    asa_transpose_qkv_kernel<<<dim3(13, 8, BB * 48), dim3(32, 8)>>>();
    asa_freq_attn_kernel<<<dim3(TT, BB), 256>>>();
    asa_transpose_fout_kernel<<<dim3(8, 13, BB * 16), dim3(32, 8)>>>();
    asa_time_attn_kernel<<<dim3(FF, BB), 416, 14016 * 4>>>(inp, w_proj,
        g3, b3, m3, v3, a3, out);
}

// round 4
// speedup vs baseline: 1.2625x; 1.2625x over previous
#include <cuda_runtime.h>
#include <cuda_bf16.h>
#include <cstdint>
#include <math.h>

#define BB 4
#define CC 64
#define FF 256
#define TT 400
#define DC 16
#define SP (FF*TT)

#define QS 0.36067376022224085f   /* 0.25 * log2(e) */

__device__ __forceinline__ float ex2f(float x) {
    float r; asm("ex2.approx.ftz.f32 %0, %1;" : "=f"(r) : "f"(x)); return r;
}
__device__ __forceinline__ uint32_t smem_u32(const void* p) {
    uint32_t a;
    asm("{ .reg .u64 t; cvta.to.shared.u64 t, %1; cvt.u32.u64 %0, t; }" : "=r"(a) : "l"(p));
    return a;
}
__device__ __forceinline__ void ldmx2(uint32_t& r0, uint32_t& r1, uint32_t a) {
    asm volatile("ldmatrix.sync.aligned.m8n8.x2.shared.b16 {%0,%1}, [%2];"
                 : "=r"(r0), "=r"(r1) : "r"(a));
}
__device__ __forceinline__ void mma16816(float* d, uint4 a, uint32_t b0, uint32_t b1) {
    asm volatile("mma.sync.aligned.m16n8k16.row.col.f32.bf16.bf16.f32 "
        "{%0,%1,%2,%3}, {%4,%5,%6,%7}, {%8,%9}, {%0,%1,%2,%3};"
        : "+f"(d[0]), "+f"(d[1]), "+f"(d[2]), "+f"(d[3])
        : "r"(a.x), "r"(a.y), "r"(a.z), "r"(a.w), "r"(b0), "r"(b1));
}
__device__ __forceinline__ uint32_t packbf2(float lo, float hi) {
    __nv_bfloat162 h;
    h.x = __float2bfloat16(lo); h.y = __float2bfloat16(hi);
    return *(uint32_t*)&h;
}

// ---------------- scratch ----------------
static __device__ float g_qkvf_t[(size_t)BB*48*FF*TT];   // [b][oc48][f][t]
static __device__ float g_qkvf_f[(size_t)BB*TT*48*FF];   // [b][t][oc48][f]
static __device__ float g_tqk2 [(size_t)BB*32*FF*TT];    // [b][oc32][f][t]
static __device__ float g_fout_t[(size_t)BB*TT*DC*FF];   // [b][t][c][f]
static __device__ float g_fout_f[(size_t)BB*FF*DC*TT];   // [b][f][c][t]
static __device__ __align__(16) uint4 g_wafH[640];       // [octile5][kstep4][lane32]
static __device__ __align__(16) uint4 g_wafL[640];
static __device__ float g_shift[80];
static __device__ float g_alpha[80];

// ================= kernel 0: prep (fold BN scale into W, pack mma A-fragments) ==========
__global__ __launch_bounds__(256)
void asa_prep_kernel(const float* __restrict__ w_fqkv, const float* __restrict__ w_tqk,
    const float* __restrict__ g1, const float* __restrict__ b1,
    const float* __restrict__ m1, const float* __restrict__ v1, const float* __restrict__ a1,
    const float* __restrict__ g2, const float* __restrict__ b2,
    const float* __restrict__ m2, const float* __restrict__ v2, const float* __restrict__ a2)
{
    int i = blockIdx.x * 256 + threadIdx.x;
    if (i < 640) {
        int lane = i & 31, ks = (i >> 5) & 3, o = i >> 7;
        int r = lane >> 2, cp = (lane & 3) * 2;
        int oc0 = o * 16 + r, k0 = ks * 16 + cp;
        uint32_t hiR[4], loR[4];
        #pragma unroll
        for (int aa = 0; aa < 4; aa++) {
            int oc = oc0 + ((aa & 1) << 3);
            int kk = k0 + ((aa >> 1) << 3);
            float s, w0, w1;
            if (oc < 48) {
                s = g1[oc] * rsqrtf(v1[oc] + 1e-5f);
                w0 = w_fqkv[oc * 64 + kk] * s; w1 = w_fqkv[oc * 64 + kk + 1] * s;
            } else {
                int j = oc - 48;
                s = g2[j] * rsqrtf(v2[j] + 1e-5f);
                w0 = w_tqk[j * 64 + kk] * s; w1 = w_tqk[j * 64 + kk + 1] * s;
            }
            __nv_bfloat16 h0 = __float2bfloat16(w0), h1 = __float2bfloat16(w1);
            float f0 = __bfloat162float(h0), f1 = __bfloat162float(h1);
            __nv_bfloat162 hh; hh.x = h0; hh.y = h1;
            __nv_bfloat162 ll; ll.x = __float2bfloat16(w0 - f0); ll.y = __float2bfloat16(w1 - f1);
            hiR[aa] = *(uint32_t*)&hh; loR[aa] = *(uint32_t*)&ll;
        }
        g_wafH[i] = make_uint4(hiR[0], hiR[1], hiR[2], hiR[3]);
        g_wafL[i] = make_uint4(loR[0], loR[1], loR[2], loR[3]);
    }
    if (i < 80) {
        float ss, sh, al;
        if (i < 48) { ss = g1[i] * rsqrtf(v1[i] + 1e-5f); sh = b1[i] - m1[i] * ss; al = a1[i]; }
        else { int j = i - 48; ss = g2[j] * rsqrtf(v2[j] + 1e-5f); sh = b2[j] - m2[j] * ss; al = a2[j]; }
        g_shift[i] = sh; g_alpha[i] = al;
    }
}

// ================= kernel 1: conv1x1 via mma.sync bf16 (3x split) ==========
// block: 320 threads (10 warps), warp -> (octile = wid/2, sptile = wid&1)
// tile: 80 oc x 64 spatial, K = 64
__global__ __launch_bounds__(320)
void asa_conv_mma_kernel(const float* __restrict__ inp)
{
    __shared__ __align__(16) char xhi[8192];   // X^T [sp64][k64] bf16, swizzled
    __shared__ __align__(16) char xlo[8192];
    int tid = threadIdx.x, wid = tid >> 5, lane = tid & 31;
    int b = blockIdx.y;
    int n0 = blockIdx.x * 64;
    const float* xb = inp + (size_t)b * CC * SP + n0;

    for (int ch = tid; ch < 512; ch += 320) {
        int sp = ch & 63, kb = ch >> 6;   // kb: 8 k-chunks of 8
        float v[8];
        #pragma unroll
        for (int j = 0; j < 8; j++) v[j] = xb[(size_t)(kb * 8 + j) * SP + sp];
        uint32_t hp[4], lp[4];
        #pragma unroll
        for (int j = 0; j < 4; j++) {
            __nv_bfloat16 h0 = __float2bfloat16(v[2*j]), h1 = __float2bfloat16(v[2*j+1]);
            __nv_bfloat162 hh; hh.x = h0; hh.y = h1;
            __nv_bfloat162 ll;
            ll.x = __float2bfloat16(v[2*j] - __bfloat162float(h0));
            ll.y = __float2bfloat16(v[2*j+1] - __bfloat162float(h1));
            hp[j] = *(uint32_t*)&hh; lp[j] = *(uint32_t*)&ll;
        }
        uint32_t off = sp * 128 + ((kb * 16) ^ ((sp & 7) << 4));
        *(uint4*)(xhi + off) = make_uint4(hp[0], hp[1], hp[2], hp[3]);
        *(uint4*)(xlo + off) = make_uint4(lp[0], lp[1], lp[2], lp[3]);
    }
    __syncthreads();

    int octile = wid >> 1, sptile = wid & 1;
    uint32_t shi = smem_u32(xhi), slo = smem_u32(xlo);
    float d[4][4];
    #pragma unroll
    for (int nt = 0; nt < 4; nt++)
        #pragma unroll
        for (int j = 0; j < 4; j++) d[nt][j] = 0.f;

    int ln = lane & 15;
    int sprow_base = sptile * 32 + (ln & 7);
    int khalf = ((ln >> 3) & 1) << 3;

    #pragma unroll
    for (int ks = 0; ks < 4; ks++) {
        uint4 ah = g_wafH[(octile * 4 + ks) * 32 + lane];
        uint4 al = g_wafL[(octile * 4 + ks) * 32 + lane];
        #pragma unroll
        for (int nt = 0; nt < 4; nt++) {
            int spr = sprow_base + nt * 8;
            int ke = ks * 16 + khalf;
            uint32_t aoff = spr * 128 + ((ke * 2) ^ ((spr & 7) << 4));
            uint32_t bh0, bh1, bl0, bl1;
            ldmx2(bh0, bh1, shi + aoff);
            ldmx2(bl0, bl1, slo + aoff);
            mma16816(d[nt], ah, bh0, bh1);
            mma16816(d[nt], al, bh0, bh1);
            mma16816(d[nt], ah, bl0, bl1);
        }
    }

    int r = lane >> 2, cp = (lane & 3) * 2;
    #pragma unroll
    for (int half = 0; half < 2; half++) {
        int oc = octile * 16 + r + half * 8;
        float sh = g_shift[oc], al = g_alpha[oc];
        float* dst;
        if (oc < 48) dst = g_qkvf_t + ((size_t)b * 48 + oc) * SP + n0;
        else         dst = g_tqk2  + ((size_t)b * 32 + (oc - 48)) * SP + n0;
        #pragma unroll
        for (int nt = 0; nt < 4; nt++) {
            float v0 = d[nt][half * 2 + 0] + sh; v0 = v0 > 0.f ? v0 : al * v0;
            float v1 = d[nt][half * 2 + 1] + sh; v1 = v1 > 0.f ? v1 : al * v1;
            int sp = sptile * 32 + nt * 8 + cp;
            *(float2*)(dst + sp) = make_float2(v0, v1);
        }
    }
}

// ================= transpose 1: [b][oc][f][t] -> [b][t][oc][f] =================
__global__ __launch_bounds__(256)
void asa_transpose_qkv_kernel()
{
    __shared__ float tile[32][33];
    int z = blockIdx.z;
    int t0 = blockIdx.x * 32, f0 = blockIdx.y * 32;
    int tx = threadIdx.x, ty = threadIdx.y;
    size_t ibase = (size_t)z * FF * TT;
    #pragma unroll
    for (int k = 0; k < 32; k += 8) {
        int t = t0 + tx, f = f0 + ty + k;
        if (t < TT) tile[ty + k][tx] = g_qkvf_t[ibase + (size_t)f * TT + t];
    }
    __syncthreads();
    int b = z / 48, oc = z % 48;
    #pragma unroll
    for (int k = 0; k < 32; k += 8) {
        int t = t0 + ty + k, f = f0 + tx;
        if (t < TT) g_qkvf_f[((size_t)(b * TT + t) * 48 + oc) * FF + f] = tile[tx][ty + k];
    }
}

// ================= kernel 2: frequency attention (no-max softmax) =================
__global__ __launch_bounds__(256)
void asa_freq_attn_kernel()
{
    __shared__ float ks[16 * 256];
    __shared__ float vs[16 * 256];
    int t = blockIdx.x, b = blockIdx.y;
    int f = threadIdx.x;
    const float* base = g_qkvf_f + (size_t)(b * TT + t) * 48 * FF;
    for (int i = f; i < 1024; i += 256) {
        ((float4*)ks)[i] = ((const float4*)(base + 4096))[i];
        ((float4*)vs)[i] = ((const float4*)(base + 8192))[i];
    }
    __syncthreads();

    float q[16];
    #pragma unroll
    for (int c = 0; c < 16; c++) q[c] = base[c * 256 + f] * QS;

    float l = 0.f, acc[16];
    #pragma unroll
    for (int c = 0; c < 16; c++) acc[c] = 0.f;

    for (int y0 = 0; y0 < 256; y0 += 32) {
        float s[32];
        #pragma unroll
        for (int i = 0; i < 32; i++) s[i] = 0.f;
        #pragma unroll 4
        for (int c = 0; c < 16; c++) {
            const float4* kp = (const float4*)(ks + c * 256 + y0);
            float qc = q[c];
            #pragma unroll
            for (int j = 0; j < 8; j++) {
                float4 k4 = kp[j];
                s[4*j+0] = fmaf(qc, k4.x, s[4*j+0]);
                s[4*j+1] = fmaf(qc, k4.y, s[4*j+1]);
                s[4*j+2] = fmaf(qc, k4.z, s[4*j+2]);
                s[4*j+3] = fmaf(qc, k4.w, s[4*j+3]);
            }
        }
        float ps = 0.f;
        #pragma unroll
        for (int i = 0; i < 32; i++) { s[i] = ex2f(s[i]); ps += s[i]; }
        l += ps;
        #pragma unroll 4
        for (int c = 0; c < 16; c++) {
            const float4* vp = (const float4*)(vs + c * 256 + y0);
            float a = acc[c];
            #pragma unroll
            for (int j = 0; j < 8; j++) {
                float4 v4 = vp[j];
                a = fmaf(s[4*j+0], v4.x, a);
                a = fmaf(s[4*j+1], v4.y, a);
                a = fmaf(s[4*j+2], v4.z, a);
                a = fmaf(s[4*j+3], v4.w, a);
            }
            acc[c] = a;
        }
    }
    float inv = 1.f / l;
    size_t ob = (size_t)(b * TT + t) * DC * FF + f;
    #pragma unroll
    for (int c = 0; c < 16; c++) g_fout_t[ob + c * 256] = acc[c] * inv;
}

// ================= transpose 2: [b][t][c][f] -> [b][f][c][t] =================
__global__ __launch_bounds__(256)
void asa_transpose_fout_kernel()
{
    __shared__ float tile[32][33];
    int z = blockIdx.z;
    int f0 = blockIdx.x * 32, t0 = blockIdx.y * 32;
    int tx = threadIdx.x, ty = threadIdx.y;
    int b = z / 16, c = z % 16;
    #pragma unroll
    for (int k = 0; k < 32; k += 8) {
        int t = t0 + ty + k, f = f0 + tx;
        if (t < TT) tile[ty + k][tx] = g_fout_t[((size_t)(b * TT + t) * DC + c) * FF + f];
    }
    __syncthreads();
    #pragma unroll
    for (int k = 0; k < 32; k += 8) {
        int f = f0 + ty + k, t = t0 + tx;
        if (t < TT) g_fout_f[((size_t)(b * FF + f) * DC + c) * TT + t] = tile[tx][ty + k];
    }
}

// ======= kernel 3: causal time attention + proj + BN + PReLU + residual =======
__global__ __launch_bounds__(416)
void asa_time_attn_kernel(const float* __restrict__ inp, const float* __restrict__ w_proj,
    const float* __restrict__ g3, const float* __restrict__ b3, const float* __restrict__ m3,
    const float* __restrict__ v3, const float* __restrict__ a3, float* __restrict__ out)
{
    extern __shared__ float sm[];
    float* kt  = sm;            // 16*400
    float* vf  = sm + 6400;     // 16*400
    float* wp  = sm + 12800;    // 64*16
    float* sc3 = sm + 13824;
    float* sh3 = sm + 13888;
    float* al3 = sm + 13952;

    int f = blockIdx.x, b = blockIdx.y;
    int tid = threadIdx.x;
    size_t cbase = (size_t)b * 32 * SP + (size_t)f * TT;
    size_t fbase = (size_t)(b * FF + f) * DC * TT;
    for (int i = tid; i < 1600; i += 416) {
        int c = i / 100, off = (i % 100) * 4;
        *(float4*)(kt + c * TT + off) = *(const float4*)(g_tqk2 + cbase + (size_t)(16 + c) * SP + off);
        ((float4*)vf)[i] = ((const float4*)(g_fout_f + fbase))[i];
    }
    for (int i = tid; i < 1024; i += 416) wp[i] = w_proj[i];
    if (tid < 64) {
        float s = g3[tid] * rsqrtf(v3[tid] + 1e-5f);
        sc3[tid] = s; sh3[tid] = b3[tid] - m3[tid] * s; al3[tid] = a3[tid];
    }
    __syncthreads();
    if (tid >= TT) return;
    int t = tid;

    float q[16];
    #pragma unroll
    for (int c = 0; c < 16; c++) q[c] = g_tqk2[cbase + (size_t)c * SP + t] * QS;

    float l = 0.f, acc[16];
    #pragma unroll
    for (int c = 0; c < 16; c++) acc[c] = 0.f;

    int nch = (t >> 5) + 1;
    for (int ch = 0; ch < nch; ch++) {
        int y0 = ch * 32;
        float s[32];
        #pragma unroll
        for (int i = 0; i < 32; i++) s[i] = 0.f;
        #pragma unroll 4
        for (int c = 0; c < 16; c++) {
            const float4* kp = (const float4*)(kt + c * TT + y0);
            float qc = q[c];
            #pragma unroll
            for (int j = 0; j < 8; j++) {
                float4 k4 = kp[j];
                s[4*j+0] = fmaf(qc, k4.x, s[4*j+0]);
                s[4*j+1] = fmaf(qc, k4.y, s[4*j+1]);
                s[4*j+2] = fmaf(qc, k4.z, s[4*j+2]);
                s[4*j+3] = fmaf(qc, k4.w, s[4*j+3]);
            }
        }
        if (y0 + 31 > t) {
            #pragma unroll
            for (int i = 0; i < 32; i++) if (y0 + i > t) s[i] = -3e38f;
        }
        float ps = 0.f;
        #pragma unroll
        for (int i = 0; i < 32; i++) { s[i] = ex2f(s[i]); ps += s[i]; }
        l += ps;
        #pragma unroll 4
        for (int c = 0; c < 16; c++) {
            const float4* vp = (const float4*)(vf + c * TT + y0);
            float a = acc[c];
            #pragma unroll
            for (int j = 0; j < 8; j++) {
                float4 v4 = vp[j];
                a = fmaf(s[4*j+0], v4.x, a);
                a = fmaf(s[4*j+1], v4.y, a);
                a = fmaf(s[4*j+2], v4.z, a);
                a = fmaf(s[4*j+3], v4.w, a);
            }
            acc[c] = a;
        }
    }
    float inv = 1.f / l;
    #pragma unroll
    for (int c = 0; c < 16; c++) acc[c] *= inv;

    size_t obase = (((size_t)b * CC) * FF + f) * TT + t;
    #pragma unroll 8
    for (int oc = 0; oc < CC; oc++) {
        const float4* wr = (const float4*)(wp + oc * 16);
        float4 w0 = wr[0], w1 = wr[1], w2 = wr[2], w3 = wr[3];
        float r = 0.f;
        r = fmaf(w0.x, acc[0],  r); r = fmaf(w0.y, acc[1],  r);
        r = fmaf(w0.z, acc[2],  r); r = fmaf(w0.w, acc[3],  r);
        r = fmaf(w1.x, acc[4],  r); r = fmaf(w1.y, acc[5],  r);
        r = fmaf(w1.z, acc[6],  r); r = fmaf(w1.w, acc[7],  r);
        r = fmaf(w2.x, acc[8],  r); r = fmaf(w2.y, acc[9],  r);
        r = fmaf(w2.z, acc[10], r); r = fmaf(w2.w, acc[11], r);
        r = fmaf(w3.x, acc[12], r); r = fmaf(w3.y, acc[13], r);
        r = fmaf(w3.z, acc[14], r); r = fmaf(w3.w, acc[15], r);
        r = fmaf(r, sc3[oc], sh3[oc]);
        r = r > 0.f ? r : al3[oc] * r;
        out[obase + (size_t)oc * SP] = r + inp[obase + (size_t)oc * SP];
    }
}

// ================= launcher =================
extern "C" void kernel_launch(void* const* d_in, const int* in_sizes, int n_in,
                              void* d_out, int out_size)
{
    (void)in_sizes; (void)n_in; (void)out_size;
    const float* inp    = (const float*)d_in[0];
    const float* w_fqkv = (const float*)d_in[2];
    const float* g1 = (const float*)d_in[3];
    const float* b1 = (const float*)d_in[4];
    const float* m1 = (const float*)d_in[5];
    const float* v1 = (const float*)d_in[6];
    const float* a1 = (const float*)d_in[7];
    const float* w_tqk  = (const float*)d_in[8];
    const float* g2 = (const float*)d_in[9];
    const float* b2 = (const float*)d_in[10];
    const float* m2 = (const float*)d_in[11];
    const float* v2 = (const float*)d_in[12];
    const float* a2 = (const float*)d_in[13];
    const float* w_proj = (const float*)d_in[14];
    const float* g3 = (const float*)d_in[15];
    const float* b3 = (const float*)d_in[16];
    const float* m3 = (const float*)d_in[17];
    const float* v3 = (const float*)d_in[18];
    const float* a3 = (const float*)d_in[19];
    float* out = (float*)d_out;

    cudaFuncSetAttribute(asa_time_attn_kernel,
                         cudaFuncAttributeMaxDynamicSharedMemorySize, 14016 * 4);

    asa_prep_kernel<<<3, 256>>>(w_fqkv, w_tqk, g1, b1, m1, v1, a1,
                                g2, b2, m2, v2, a2);
    asa_conv_mma_kernel<<<dim3(1600, BB), 320>>>(inp);
    asa_transpose_qkv_kernel<<<dim3(13, 8, BB * 48), dim3(32, 8)>>>();
    asa_freq_attn_kernel<<<dim3(TT, BB), 256>>>();
    asa_transpose_fout_kernel<<<dim3(8, 13, BB * 16), dim3(32, 8)>>>();
    asa_time_attn_kernel<<<dim3(FF, BB), 416, 14016 * 4>>>(inp, w_proj,
        g3, b3, m3, v3, a3, out);
}

// round 6
// speedup vs baseline: 1.3951x; 1.1051x over previous
#include <cuda_runtime.h>
#include <cuda_bf16.h>
#include <cstdint>
#include <math.h>

#define BB 4
#define CC 64
#define FF 256
#define TT 400
#define DC 16
#define SP (FF*TT)

#define QS 0.36067376022224085f   /* 0.25 * log2(e) */

__device__ __forceinline__ float ex2f(float x) {
    float r; asm("ex2.approx.ftz.f32 %0, %1;" : "=f"(r) : "f"(x)); return r;
}
__device__ __forceinline__ uint32_t smem_u32(const void* p) {
    uint32_t a;
    asm("{ .reg .u64 t; cvta.to.shared.u64 t, %1; cvt.u32.u64 %0, t; }" : "=r"(a) : "l"(p));
    return a;
}
__device__ __forceinline__ void ldmx2(uint32_t& r0, uint32_t& r1, uint32_t a) {
    asm volatile("ldmatrix.sync.aligned.m8n8.x2.shared.b16 {%0,%1}, [%2];"
                 : "=r"(r0), "=r"(r1) : "r"(a));
}
__device__ __forceinline__ void mma16816(float* d, uint4 a, uint32_t b0, uint32_t b1) {
    asm volatile("mma.sync.aligned.m16n8k16.row.col.f32.bf16.bf16.f32 "
        "{%0,%1,%2,%3}, {%4,%5,%6,%7}, {%8,%9}, {%0,%1,%2,%3};"
        : "+f"(d[0]), "+f"(d[1]), "+f"(d[2]), "+f"(d[3])
        : "r"(a.x), "r"(a.y), "r"(a.z), "r"(a.w), "r"(b0), "r"(b1));
}

// ---------------- scratch ----------------
static __device__ float g_qkvf_t[(size_t)BB*48*FF*TT];   // [b][oc48][f][t]
static __device__ float g_qkvf_f[(size_t)BB*TT*48*FF];   // [b][t][oc48][f]
static __device__ float g_tqk2 [(size_t)BB*32*FF*TT];    // [b][oc32][f][t]
static __device__ float g_fout_t[(size_t)BB*TT*DC*FF];   // [b][t][c][f]
static __device__ float g_fout_f[(size_t)BB*FF*DC*TT];   // [b][f][c][t]
static __device__ __align__(16) uint4 g_wafH[640];       // [octile5][kstep4][lane32]
static __device__ __align__(16) uint4 g_wafL[640];
static __device__ float g_shift[80];
static __device__ float g_alpha[80];

// ================= kernel 0: prep =================
__global__ __launch_bounds__(256)
void asa_prep_kernel(const float* __restrict__ w_fqkv, const float* __restrict__ w_tqk,
    const float* __restrict__ g1, const float* __restrict__ b1,
    const float* __restrict__ m1, const float* __restrict__ v1, const float* __restrict__ a1,
    const float* __restrict__ g2, const float* __restrict__ b2,
    const float* __restrict__ m2, const float* __restrict__ v2, const float* __restrict__ a2)
{
    int i = blockIdx.x * 256 + threadIdx.x;
    if (i < 640) {
        int lane = i & 31, ks = (i >> 5) & 3, o = i >> 7;
        int r = lane >> 2, cp = (lane & 3) * 2;
        int oc0 = o * 16 + r, k0 = ks * 16 + cp;
        uint32_t hiR[4], loR[4];
        #pragma unroll
        for (int aa = 0; aa < 4; aa++) {
            int oc = oc0 + ((aa & 1) << 3);
            int kk = k0 + ((aa >> 1) << 3);
            float s, w0, w1;
            if (oc < 48) {
                s = g1[oc] * rsqrtf(v1[oc] + 1e-5f);
                w0 = w_fqkv[oc * 64 + kk] * s; w1 = w_fqkv[oc * 64 + kk + 1] * s;
            } else {
                int j = oc - 48;
                s = g2[j] * rsqrtf(v2[j] + 1e-5f);
                w0 = w_tqk[j * 64 + kk] * s; w1 = w_tqk[j * 64 + kk + 1] * s;
            }
            __nv_bfloat16 h0 = __float2bfloat16(w0), h1 = __float2bfloat16(w1);
            float f0 = __bfloat162float(h0), f1 = __bfloat162float(h1);
            __nv_bfloat162 hh; hh.x = h0; hh.y = h1;
            __nv_bfloat162 ll; ll.x = __float2bfloat16(w0 - f0); ll.y = __float2bfloat16(w1 - f1);
            hiR[aa] = *(uint32_t*)&hh; loR[aa] = *(uint32_t*)&ll;
        }
        g_wafH[i] = make_uint4(hiR[0], hiR[1], hiR[2], hiR[3]);
        g_wafL[i] = make_uint4(loR[0], loR[1], loR[2], loR[3]);
    }
    if (i < 80) {
        float ss, sh, al;
        if (i < 48) { ss = g1[i] * rsqrtf(v1[i] + 1e-5f); sh = b1[i] - m1[i] * ss; al = a1[i]; }
        else { int j = i - 48; ss = g2[j] * rsqrtf(v2[j] + 1e-5f); sh = b2[j] - m2[j] * ss; al = a2[j]; }
        g_shift[i] = sh; g_alpha[i] = al;
    }
}

// ================= kernel 1: conv1x1 via mma.sync bf16 (3x split) ==========
__global__ __launch_bounds__(320)
void asa_conv_mma_kernel(const float* __restrict__ inp)
{
    __shared__ __align__(16) char xhi[8192];
    __shared__ __align__(16) char xlo[8192];
    int tid = threadIdx.x, wid = tid >> 5, lane = tid & 31;
    int b = blockIdx.y;
    int n0 = blockIdx.x * 64;
    const float* xb = inp + (size_t)b * CC * SP + n0;

    for (int ch = tid; ch < 512; ch += 320) {
        int sp = ch & 63, kb = ch >> 6;
        float v[8];
        #pragma unroll
        for (int j = 0; j < 8; j++) v[j] = xb[(size_t)(kb * 8 + j) * SP + sp];
        uint32_t hp[4], lp[4];
        #pragma unroll
        for (int j = 0; j < 4; j++) {
            __nv_bfloat16 h0 = __float2bfloat16(v[2*j]), h1 = __float2bfloat16(v[2*j+1]);
            __nv_bfloat162 hh; hh.x = h0; hh.y = h1;
            __nv_bfloat162 ll;
            ll.x = __float2bfloat16(v[2*j] - __bfloat162float(h0));
            ll.y = __float2bfloat16(v[2*j+1] - __bfloat162float(h1));
            hp[j] = *(uint32_t*)&hh; lp[j] = *(uint32_t*)&ll;
        }
        uint32_t off = sp * 128 + ((kb * 16) ^ ((sp & 7) << 4));
        *(uint4*)(xhi + off) = make_uint4(hp[0], hp[1], hp[2], hp[3]);
        *(uint4*)(xlo + off) = make_uint4(lp[0], lp[1], lp[2], lp[3]);
    }
    __syncthreads();

    int octile = wid >> 1, sptile = wid & 1;
    uint32_t shi = smem_u32(xhi), slo = smem_u32(xlo);
    float d[4][4];
    #pragma unroll
    for (int nt = 0; nt < 4; nt++)
        #pragma unroll
        for (int j = 0; j < 4; j++) d[nt][j] = 0.f;

    int ln = lane & 15;
    int sprow_base = sptile * 32 + (ln & 7);
    int khalf = ((ln >> 3) & 1) << 3;

    #pragma unroll
    for (int ks = 0; ks < 4; ks++) {
        uint4 ah = g_wafH[(octile * 4 + ks) * 32 + lane];
        uint4 al = g_wafL[(octile * 4 + ks) * 32 + lane];
        #pragma unroll
        for (int nt = 0; nt < 4; nt++) {
            int spr = sprow_base + nt * 8;
            int ke = ks * 16 + khalf;
            uint32_t aoff = spr * 128 + ((ke * 2) ^ ((spr & 7) << 4));
            uint32_t bh0, bh1, bl0, bl1;
            ldmx2(bh0, bh1, shi + aoff);
            ldmx2(bl0, bl1, slo + aoff);
            mma16816(d[nt], ah, bh0, bh1);
            mma16816(d[nt], al, bh0, bh1);
            mma16816(d[nt], ah, bl0, bl1);
        }
    }

    int r = lane >> 2, cp = (lane & 3) * 2;
    #pragma unroll
    for (int half = 0; half < 2; half++) {
        int oc = octile * 16 + r + half * 8;
        float sh = g_shift[oc], al = g_alpha[oc];
        float* dst;
        if (oc < 48) dst = g_qkvf_t + ((size_t)b * 48 + oc) * SP + n0;
        else         dst = g_tqk2  + ((size_t)b * 32 + (oc - 48)) * SP + n0;
        #pragma unroll
        for (int nt = 0; nt < 4; nt++) {
            float v0 = d[nt][half * 2 + 0] + sh; v0 = v0 > 0.f ? v0 : al * v0;
            float v1 = d[nt][half * 2 + 1] + sh; v1 = v1 > 0.f ? v1 : al * v1;
            int sp = sptile * 32 + nt * 8 + cp;
            *(float2*)(dst + sp) = make_float2(v0, v1);
        }
    }
}

// ================= transpose 1 =================
__global__ __launch_bounds__(256)
void asa_transpose_qkv_kernel()
{
    __shared__ float tile[32][33];
    int z = blockIdx.z;
    int t0 = blockIdx.x * 32, f0 = blockIdx.y * 32;
    int tx = threadIdx.x, ty = threadIdx.y;
    size_t ibase = (size_t)z * FF * TT;
    #pragma unroll
    for (int k = 0; k < 32; k += 8) {
        int t = t0 + tx, f = f0 + ty + k;
        if (t < TT) tile[ty + k][tx] = g_qkvf_t[ibase + (size_t)f * TT + t];
    }
    __syncthreads();
    int b = z / 48, oc = z % 48;
    #pragma unroll
    for (int k = 0; k < 32; k += 8) {
        int t = t0 + ty + k, f = f0 + tx;
        if (t < TT) g_qkvf_f[((size_t)(b * TT + t) * 48 + oc) * FF + f] = tile[tx][ty + k];
    }
}

// ========== kernel 2: frequency attention, 2 f-columns per thread ==========
__global__ __launch_bounds__(128, 4)
void asa_freq_attn_kernel()
{
    __shared__ float ks[16 * 256];
    __shared__ float vs[16 * 256];
    int t = blockIdx.x, b = blockIdx.y;
    int tid = threadIdx.x;
    const float* base = g_qkvf_f + (size_t)(b * TT + t) * 48 * FF;
    for (int i = tid; i < 1024; i += 128) {
        ((float4*)ks)[i] = ((const float4*)(base + 4096))[i];
        ((float4*)vs)[i] = ((const float4*)(base + 8192))[i];
    }
    __syncthreads();

    int f0 = tid, f1 = tid + 128;
    float qA[16], qB[16];
    #pragma unroll
    for (int c = 0; c < 16; c++) {
        qA[c] = base[c * 256 + f0] * QS;
        qB[c] = base[c * 256 + f1] * QS;
    }

    float lA = 0.f, lB = 0.f, accA[16], accB[16];
    #pragma unroll
    for (int c = 0; c < 16; c++) { accA[c] = 0.f; accB[c] = 0.f; }

    for (int y0 = 0; y0 < 256; y0 += 16) {
        float sA[16], sB[16];
        #pragma unroll
        for (int i = 0; i < 16; i++) { sA[i] = 0.f; sB[i] = 0.f; }
        #pragma unroll 4
        for (int c = 0; c < 16; c++) {
            const float4* kp = (const float4*)(ks + c * 256 + y0);
            float qa = qA[c], qb = qB[c];
            #pragma unroll
            for (int j = 0; j < 4; j++) {
                float4 k4 = kp[j];
                sA[4*j+0] = fmaf(qa, k4.x, sA[4*j+0]); sB[4*j+0] = fmaf(qb, k4.x, sB[4*j+0]);
                sA[4*j+1] = fmaf(qa, k4.y, sA[4*j+1]); sB[4*j+1] = fmaf(qb, k4.y, sB[4*j+1]);
                sA[4*j+2] = fmaf(qa, k4.z, sA[4*j+2]); sB[4*j+2] = fmaf(qb, k4.z, sB[4*j+2]);
                sA[4*j+3] = fmaf(qa, k4.w, sA[4*j+3]); sB[4*j+3] = fmaf(qb, k4.w, sB[4*j+3]);
            }
        }
        float pa = 0.f, pb = 0.f;
        #pragma unroll
        for (int i = 0; i < 16; i++) {
            sA[i] = ex2f(sA[i]); pa += sA[i];
            sB[i] = ex2f(sB[i]); pb += sB[i];
        }
        lA += pa; lB += pb;
        #pragma unroll 4
        for (int c = 0; c < 16; c++) {
            const float4* vp = (const float4*)(vs + c * 256 + y0);
            float a = accA[c], bb2 = accB[c];
            #pragma unroll
            for (int j = 0; j < 4; j++) {
                float4 v4 = vp[j];
                a   = fmaf(sA[4*j+0], v4.x, a);   bb2 = fmaf(sB[4*j+0], v4.x, bb2);
                a   = fmaf(sA[4*j+1], v4.y, a);   bb2 = fmaf(sB[4*j+1], v4.y, bb2);
                a   = fmaf(sA[4*j+2], v4.z, a);   bb2 = fmaf(sB[4*j+2], v4.z, bb2);
                a   = fmaf(sA[4*j+3], v4.w, a);   bb2 = fmaf(sB[4*j+3], v4.w, bb2);
            }
            accA[c] = a; accB[c] = bb2;
        }
    }
    float invA = 1.f / lA, invB = 1.f / lB;
    size_t ob = (size_t)(b * TT + t) * DC * FF;
    #pragma unroll
    for (int c = 0; c < 16; c++) {
        g_fout_t[ob + c * 256 + f0] = accA[c] * invA;
        g_fout_t[ob + c * 256 + f1] = accB[c] * invB;
    }
}

// ================= transpose 2 =================
__global__ __launch_bounds__(256)
void asa_transpose_fout_kernel()
{
    __shared__ float tile[32][33];
    int z = blockIdx.z;
    int f0 = blockIdx.x * 32, t0 = blockIdx.y * 32;
    int tx = threadIdx.x, ty = threadIdx.y;
    int b = z / 16, c = z % 16;
    #pragma unroll
    for (int k = 0; k < 32; k += 8) {
        int t = t0 + ty + k, f = f0 + tx;
        if (t < TT) tile[ty + k][tx] = g_fout_t[((size_t)(b * TT + t) * DC + c) * FF + f];
    }
    __syncthreads();
    #pragma unroll
    for (int k = 0; k < 32; k += 8) {
        int f = f0 + ty + k, t = t0 + tx;
        if (t < TT) g_fout_f[((size_t)(b * FF + f) * DC + c) * TT + t] = tile[tx][ty + k];
    }
}

// ======= kernel 3: causal time attention, adjacent-row pair per thread =======
__global__ __launch_bounds__(256, 2)
void asa_time_attn_kernel(const float* __restrict__ inp, const float* __restrict__ w_proj,
    const float* __restrict__ g3, const float* __restrict__ b3, const float* __restrict__ m3,
    const float* __restrict__ v3, const float* __restrict__ a3, float* __restrict__ out)
{
    extern __shared__ float sm[];
    float* kt  = sm;            // 16*400
    float* vf  = sm + 6400;     // 16*400
    float* wp  = sm + 12800;    // 64*16
    float* sc3 = sm + 13824;
    float* sh3 = sm + 13888;
    float* al3 = sm + 13952;

    int f = blockIdx.x, b = blockIdx.y;
    int tid = threadIdx.x;
    size_t cbase = (size_t)b * 32 * SP + (size_t)f * TT;
    size_t fbase = (size_t)(b * FF + f) * DC * TT;
    for (int i = tid; i < 1600; i += 256) {
        int c = i / 100, off = (i % 100) * 4;
        *(float4*)(kt + c * TT + off) = *(const float4*)(g_tqk2 + cbase + (size_t)(16 + c) * SP + off);
        ((float4*)vf)[i] = ((const float4*)(g_fout_f + fbase))[i];
    }
    for (int i = tid; i < 1024; i += 256) wp[i] = w_proj[i];
    if (tid < 64) {
        float s = g3[tid] * rsqrtf(v3[tid] + 1e-5f);
        sc3[tid] = s; sh3[tid] = b3[tid] - m3[tid] * s; al3[tid] = a3[tid];
    }
    __syncthreads();
    if (tid >= 200) return;

    int tA = 2 * tid, tB = tA + 1;
    int cB = tB >> 4;            // final chunk index (shared loop bound)
    int limA = tA - (cB << 4);   // may be -1 (then A fully masked in final chunk)
    int limB = tB - (cB << 4);

    float qA[16], qB[16];
    #pragma unroll
    for (int c = 0; c < 16; c++) {
        float2 qv = *(const float2*)(g_tqk2 + cbase + (size_t)c * SP + tA);
        qA[c] = qv.x * QS; qB[c] = qv.y * QS;
    }

    float lA = 0.f, lB = 0.f, accA[16], accB[16];
    #pragma unroll
    for (int c = 0; c < 16; c++) { accA[c] = 0.f; accB[c] = 0.f; }

    for (int ch = 0; ch <= cB; ch++) {
        int y0 = ch * 16;
        float sA[16], sB[16];
        #pragma unroll
        for (int i = 0; i < 16; i++) { sA[i] = 0.f; sB[i] = 0.f; }
        #pragma unroll 4
        for (int c = 0; c < 16; c++) {
            const float4* kp = (const float4*)(kt + c * TT + y0);
            float qa = qA[c], qb = qB[c];
            #pragma unroll
            for (int j = 0; j < 4; j++) {
                float4 k4 = kp[j];
                sA[4*j+0] = fmaf(qa, k4.x, sA[4*j+0]); sB[4*j+0] = fmaf(qb, k4.x, sB[4*j+0]);
                sA[4*j+1] = fmaf(qa, k4.y, sA[4*j+1]); sB[4*j+1] = fmaf(qb, k4.y, sB[4*j+1]);
                sA[4*j+2] = fmaf(qa, k4.z, sA[4*j+2]); sB[4*j+2] = fmaf(qb, k4.z, sB[4*j+2]);
                sA[4*j+3] = fmaf(qa, k4.w, sA[4*j+3]); sB[4*j+3] = fmaf(qb, k4.w, sB[4*j+3]);
            }
        }
        if (ch == cB) {
            #pragma unroll
            for (int i = 0; i < 16; i++) {
                if (i > limA) sA[i] = -3e38f;
                if (i > limB) sB[i] = -3e38f;
            }
        }
        float pa = 0.f, pb = 0.f;
        #pragma unroll
        for (int i = 0; i < 16; i++) {
            sA[i] = ex2f(sA[i]); pa += sA[i];
            sB[i] = ex2f(sB[i]); pb += sB[i];
        }
        lA += pa; lB += pb;
        #pragma unroll 4
        for (int c = 0; c < 16; c++) {
            const float4* vp = (const float4*)(vf + c * TT + y0);
            float a = accA[c], bb2 = accB[c];
            #pragma unroll
            for (int j = 0; j < 4; j++) {
                float4 v4 = vp[j];
                a   = fmaf(sA[4*j+0], v4.x, a);   bb2 = fmaf(sB[4*j+0], v4.x, bb2);
                a   = fmaf(sA[4*j+1], v4.y, a);   bb2 = fmaf(sB[4*j+1], v4.y, bb2);
                a   = fmaf(sA[4*j+2], v4.z, a);   bb2 = fmaf(sB[4*j+2], v4.z, bb2);
                a   = fmaf(sA[4*j+3], v4.w, a);   bb2 = fmaf(sB[4*j+3], v4.w, bb2);
            }
            accA[c] = a; accB[c] = bb2;
        }
    }

    float invA = 1.f / lA, invB = 1.f / lB;
    float aA[16], aB[16];
    #pragma unroll
    for (int c = 0; c < 16; c++) { aA[c] = accA[c] * invA; aB[c] = accB[c] * invB; }

    size_t obase = (((size_t)b * CC) * FF + f) * TT + tA;
    #pragma unroll 8
    for (int oc = 0; oc < CC; oc++) {
        const float4* wr = (const float4*)(wp + oc * 16);
        float4 w0 = wr[0], w1 = wr[1], w2 = wr[2], w3 = wr[3];
        float rA = 0.f, rB = 0.f;
        rA = fmaf(w0.x, aA[0],  rA); rB = fmaf(w0.x, aB[0],  rB);
        rA = fmaf(w0.y, aA[1],  rA); rB = fmaf(w0.y, aB[1],  rB);
        rA = fmaf(w0.z, aA[2],  rA); rB = fmaf(w0.z, aB[2],  rB);
        rA = fmaf(w0.w, aA[3],  rA); rB = fmaf(w0.w, aB[3],  rB);
        rA = fmaf(w1.x, aA[4],  rA); rB = fmaf(w1.x, aB[4],  rB);
        rA = fmaf(w1.y, aA[5],  rA); rB = fmaf(w1.y, aB[5],  rB);
        rA = fmaf(w1.z, aA[6],  rA); rB = fmaf(w1.z, aB[6],  rB);
        rA = fmaf(w1.w, aA[7],  rA); rB = fmaf(w1.w, aB[7],  rB);
        rA = fmaf(w2.x, aA[8],  rA); rB = fmaf(w2.x, aB[8],  rB);
        rA = fmaf(w2.y, aA[9],  rA); rB = fmaf(w2.y, aB[9],  rB);
        rA = fmaf(w2.z, aA[10], rA); rB = fmaf(w2.z, aB[10], rB);
        rA = fmaf(w2.w, aA[11], rA); rB = fmaf(w2.w, aB[11], rB);
        rA = fmaf(w3.x, aA[12], rA); rB = fmaf(w3.x, aB[12], rB);
        rA = fmaf(w3.y, aA[13], rA); rB = fmaf(w3.y, aB[13], rB);
        rA = fmaf(w3.z, aA[14], rA); rB = fmaf(w3.z, aB[14], rB);
        rA = fmaf(w3.w, aA[15], rA); rB = fmaf(w3.w, aB[15], rB);
        float sc = sc3[oc], sh = sh3[oc], al = al3[oc];
        rA = fmaf(rA, sc, sh); rA = rA > 0.f ? rA : al * rA;
        rB = fmaf(rB, sc, sh); rB = rB > 0.f ? rB : al * rB;
        float2 res = *(const float2*)(inp + obase + (size_t)oc * SP);
        *(float2*)(out + obase + (size_t)oc * SP) = make_float2(rA + res.x, rB + res.y);
    }
}

// ================= launcher =================
extern "C" void kernel_launch(void* const* d_in, const int* in_sizes, int n_in,
                              void* d_out, int out_size)
{
    (void)in_sizes; (void)n_in; (void)out_size;
    const float* inp    = (const float*)d_in[0];
    const float* w_fqkv = (const float*)d_in[2];
    const float* g1 = (const float*)d_in[3];
    const float* b1 = (const float*)d_in[4];
    const float* m1 = (const float*)d_in[5];
    const float* v1 = (const float*)d_in[6];
    const float* a1 = (const float*)d_in[7];
    const float* w_tqk  = (const float*)d_in[8];
    const float* g2 = (const float*)d_in[9];
    const float* b2 = (const float*)d_in[10];
    const float* m2 = (const float*)d_in[11];
    const float* v2 = (const float*)d_in[12];
    const float* a2 = (const float*)d_in[13];
    const float* w_proj = (const float*)d_in[14];
    const float* g3 = (const float*)d_in[15];
    const float* b3 = (const float*)d_in[16];
    const float* m3 = (const float*)d_in[17];
    const float* v3 = (const float*)d_in[18];
    const float* a3 = (const float*)d_in[19];
    float* out = (float*)d_out;

    cudaFuncSetAttribute(asa_time_attn_kernel,
                         cudaFuncAttributeMaxDynamicSharedMemorySize, 14016 * 4);

    asa_prep_kernel<<<3, 256>>>(w_fqkv, w_tqk, g1, b1, m1, v1, a1,
                                g2, b2, m2, v2, a2);
    asa_conv_mma_kernel<<<dim3(1600, BB), 320>>>(inp);
    asa_transpose_qkv_kernel<<<dim3(13, 8, BB * 48), dim3(32, 8)>>>();
    asa_freq_attn_kernel<<<dim3(TT, BB), 128>>>();
    asa_transpose_fout_kernel<<<dim3(8, 13, BB * 16), dim3(32, 8)>>>();
    asa_time_attn_kernel<<<dim3(FF, BB), 256, 14016 * 4>>>(inp, w_proj,
        g3, b3, m3, v3, a3, out);
}

// round 7
// speedup vs baseline: 1.7773x; 1.2739x over previous
#include <cuda_runtime.h>
#include <cuda_bf16.h>
#include <cstdint>
#include <math.h>

#define BB 4
#define CC 64
#define FF 256
#define TT 400
#define DC 16
#define SP (FF*TT)

#define QS 0.36067376022224085f   /* 0.25 * log2(e) */

__device__ __forceinline__ float ex2f(float x) {
    float r; asm("ex2.approx.ftz.f32 %0, %1;" : "=f"(r) : "f"(x)); return r;
}
__device__ __forceinline__ uint32_t smem_u32(const void* p) {
    uint32_t a;
    asm("{ .reg .u64 t; cvta.to.shared.u64 t, %1; cvt.u32.u64 %0, t; }" : "=r"(a) : "l"(p));
    return a;
}
__device__ __forceinline__ void ldmx2(uint32_t& r0, uint32_t& r1, uint32_t a) {
    asm volatile("ldmatrix.sync.aligned.m8n8.x2.shared.b16 {%0,%1}, [%2];"
                 : "=r"(r0), "=r"(r1) : "r"(a));
}
__device__ __forceinline__ void ldmx4(uint4& r, uint32_t a) {
    asm volatile("ldmatrix.sync.aligned.m8n8.x4.shared.b16 {%0,%1,%2,%3}, [%4];"
                 : "=r"(r.x), "=r"(r.y), "=r"(r.z), "=r"(r.w) : "r"(a));
}
__device__ __forceinline__ void mma16816(float* d, uint4 a, uint32_t b0, uint32_t b1) {
    asm volatile("mma.sync.aligned.m16n8k16.row.col.f32.bf16.bf16.f32 "
        "{%0,%1,%2,%3}, {%4,%5,%6,%7}, {%8,%9}, {%0,%1,%2,%3};"
        : "+f"(d[0]), "+f"(d[1]), "+f"(d[2]), "+f"(d[3])
        : "r"(a.x), "r"(a.y), "r"(a.z), "r"(a.w), "r"(b0), "r"(b1));
}
// pack two f32 -> bf16x2 {lo=a, hi=b}
#define PACKBF(r, a, b) asm("cvt.rn.bf16x2.f32 %0, %1, %2;" : "=r"(r) : "f"(b), "f"(a))

// ---------------- scratch ----------------
static __device__ float g_qkvf_t[(size_t)BB*48*FF*TT];   // [b][oc48][f][t]
static __device__ float g_qkvf_f[(size_t)BB*TT*48*FF];   // [b][t][oc48][f]
static __device__ float g_tqk2 [(size_t)BB*32*FF*TT];    // [b][oc32][f][t]
static __device__ float g_fout_t[(size_t)BB*TT*DC*FF];   // [b][t][c][f]
static __device__ float g_fout_f[(size_t)BB*FF*DC*TT];   // [b][f][c][t]
static __device__ __align__(16) uint4 g_wafH[640];
static __device__ __align__(16) uint4 g_wafL[640];
static __device__ float g_shift[80];
static __device__ float g_alpha[80];

// ================= kernel 0: prep =================
__global__ __launch_bounds__(256)
void asa_prep_kernel(const float* __restrict__ w_fqkv, const float* __restrict__ w_tqk,
    const float* __restrict__ g1, const float* __restrict__ b1,
    const float* __restrict__ m1, const float* __restrict__ v1, const float* __restrict__ a1,
    const float* __restrict__ g2, const float* __restrict__ b2,
    const float* __restrict__ m2, const float* __restrict__ v2, const float* __restrict__ a2)
{
    int i = blockIdx.x * 256 + threadIdx.x;
    if (i < 640) {
        int lane = i & 31, ks = (i >> 5) & 3, o = i >> 7;
        int r = lane >> 2, cp = (lane & 3) * 2;
        int oc0 = o * 16 + r, k0 = ks * 16 + cp;
        uint32_t hiR[4], loR[4];
        #pragma unroll
        for (int aa = 0; aa < 4; aa++) {
            int oc = oc0 + ((aa & 1) << 3);
            int kk = k0 + ((aa >> 1) << 3);
            float s, w0, w1;
            if (oc < 48) {
                s = g1[oc] * rsqrtf(v1[oc] + 1e-5f);
                w0 = w_fqkv[oc * 64 + kk] * s; w1 = w_fqkv[oc * 64 + kk + 1] * s;
            } else {
                int j = oc - 48;
                s = g2[j] * rsqrtf(v2[j] + 1e-5f);
                w0 = w_tqk[j * 64 + kk] * s; w1 = w_tqk[j * 64 + kk + 1] * s;
            }
            uint32_t h; PACKBF(h, w0, w1);
            float r0 = __uint_as_float(h << 16);
            float r1 = __uint_as_float(h & 0xffff0000u);
            uint32_t l; PACKBF(l, w0 - r0, w1 - r1);
            hiR[aa] = h; loR[aa] = l;
        }
        g_wafH[i] = make_uint4(hiR[0], hiR[1], hiR[2], hiR[3]);
        g_wafL[i] = make_uint4(loR[0], loR[1], loR[2], loR[3]);
    }
    if (i < 80) {
        float ss, sh, al;
        if (i < 48) { ss = g1[i] * rsqrtf(v1[i] + 1e-5f); sh = b1[i] - m1[i] * ss; al = a1[i]; }
        else { int j = i - 48; ss = g2[j] * rsqrtf(v2[j] + 1e-5f); sh = b2[j] - m2[j] * ss; al = a2[j]; }
        g_shift[i] = sh; g_alpha[i] = al;
    }
}

// ================= kernel 1: conv1x1 via mma.sync bf16 =================
__global__ __launch_bounds__(320)
void asa_conv_mma_kernel(const float* __restrict__ inp)
{
    __shared__ __align__(16) char xhi[8192];
    __shared__ __align__(16) char xlo[8192];
    int tid = threadIdx.x, wid = tid >> 5, lane = tid & 31;
    int b = blockIdx.y;
    int n0 = blockIdx.x * 64;
    const float* xb = inp + (size_t)b * CC * SP + n0;

    for (int ch = tid; ch < 512; ch += 320) {
        int sp = ch & 63, kb = ch >> 6;
        float v[8];
        #pragma unroll
        for (int j = 0; j < 8; j++) v[j] = xb[(size_t)(kb * 8 + j) * SP + sp];
        uint32_t hp[4], lp[4];
        #pragma unroll
        for (int j = 0; j < 4; j++) {
            uint32_t h; PACKBF(h, v[2*j], v[2*j+1]);
            float r0 = __uint_as_float(h << 16);
            float r1 = __uint_as_float(h & 0xffff0000u);
            uint32_t l; PACKBF(l, v[2*j] - r0, v[2*j+1] - r1);
            hp[j] = h; lp[j] = l;
        }
        uint32_t off = sp * 128 + ((kb * 16) ^ ((sp & 7) << 4));
        *(uint4*)(xhi + off) = make_uint4(hp[0], hp[1], hp[2], hp[3]);
        *(uint4*)(xlo + off) = make_uint4(lp[0], lp[1], lp[2], lp[3]);
    }
    __syncthreads();

    int octile = wid >> 1, sptile = wid & 1;
    uint32_t shi = smem_u32(xhi), slo = smem_u32(xlo);
    float d[4][4];
    #pragma unroll
    for (int nt = 0; nt < 4; nt++)
        #pragma unroll
        for (int j = 0; j < 4; j++) d[nt][j] = 0.f;

    int ln = lane & 15;
    int sprow_base = sptile * 32 + (ln & 7);
    int khalf = ((ln >> 3) & 1) << 3;

    #pragma unroll
    for (int ks = 0; ks < 4; ks++) {
        uint4 ah = g_wafH[(octile * 4 + ks) * 32 + lane];
        uint4 al = g_wafL[(octile * 4 + ks) * 32 + lane];
        #pragma unroll
        for (int nt = 0; nt < 4; nt++) {
            int spr = sprow_base + nt * 8;
            int ke = ks * 16 + khalf;
            uint32_t aoff = spr * 128 + ((ke * 2) ^ ((spr & 7) << 4));
            uint32_t bh0, bh1, bl0, bl1;
            ldmx2(bh0, bh1, shi + aoff);
            ldmx2(bl0, bl1, slo + aoff);
            mma16816(d[nt], ah, bh0, bh1);
            mma16816(d[nt], al, bh0, bh1);
            mma16816(d[nt], ah, bl0, bl1);
        }
    }

    int r = lane >> 2, cp = (lane & 3) * 2;
    #pragma unroll
    for (int half = 0; half < 2; half++) {
        int oc = octile * 16 + r + half * 8;
        float sh = g_shift[oc], al = g_alpha[oc];
        float* dst;
        if (oc < 48) dst = g_qkvf_t + ((size_t)b * 48 + oc) * SP + n0;
        else         dst = g_tqk2  + ((size_t)b * 32 + (oc - 48)) * SP + n0;
        #pragma unroll
        for (int nt = 0; nt < 4; nt++) {
            float v0 = d[nt][half * 2 + 0] + sh; v0 = v0 > 0.f ? v0 : al * v0;
            float v1 = d[nt][half * 2 + 1] + sh; v1 = v1 > 0.f ? v1 : al * v1;
            int sp = sptile * 32 + nt * 8 + cp;
            *(float2*)(dst + sp) = make_float2(v0, v1);
        }
    }
}

// ================= transpose 1 =================
__global__ __launch_bounds__(256)
void asa_transpose_qkv_kernel()
{
    __shared__ float tile[32][33];
    int z = blockIdx.z;
    int t0 = blockIdx.x * 32, f0 = blockIdx.y * 32;
    int tx = threadIdx.x, ty = threadIdx.y;
    size_t ibase = (size_t)z * FF * TT;
    #pragma unroll
    for (int k = 0; k < 32; k += 8) {
        int t = t0 + tx, f = f0 + ty + k;
        if (t < TT) tile[ty + k][tx] = g_qkvf_t[ibase + (size_t)f * TT + t];
    }
    __syncthreads();
    int b = z / 48, oc = z % 48;
    #pragma unroll
    for (int k = 0; k < 32; k += 8) {
        int t = t0 + ty + k, f = f0 + tx;
        if (t < TT) g_qkvf_f[((size_t)(b * TT + t) * 48 + oc) * FF + f] = tile[tx][ty + k];
    }
}

// ========== kernel 2: frequency attention via mma.sync (flash-style) ==========
// smem: Qhi[0,8K) Qlo[8K,16K) rows f: 32B  |  Khi[16K,24K) Klo[24K,32K) rows y: 32B
//       VThi[32K,40K) VTlo[40K,48K) rows c: 512B.  Stage f32[16c][256f] reuses Q region.
#define FQ_QHI 0
#define FQ_QLO 8192
#define FQ_KHI 16384
#define FQ_KLO 24576
#define FQ_VHI 32768
#define FQ_VLO 40960

__global__ __launch_bounds__(128)
void asa_freq_attn_kernel()
{
    __shared__ __align__(16) char smf[49152];
    int tid = threadIdx.x, wid = tid >> 5, lane = tid & 31;
    int t = blockIdx.x, b = blockIdx.y;
    const float* base = g_qkvf_f + (size_t)(b * TT + t) * 48 * FF;
    uint32_t sb = smem_u32(smf);

    // fill: Q (scaled, hi/lo), K (hi/lo) as [row][16c] 32B rows; V as VT [c][256y] 512B rows
    for (int it = 0; it < 16; it++) {
        int idx = it * 128 + tid;
        int row = idx & 255;
        int cp = idx >> 8;          // 0..7 (c pair)
        uint32_t qkoff = (uint32_t)(row * 32 + cp * 4) ^ (uint32_t)(((row >> 2) & 1) << 4);
        {
            float x0 = base[(2*cp) * 256 + row] * QS;
            float x1 = base[(2*cp+1) * 256 + row] * QS;
            uint32_t h; PACKBF(h, x0, x1);
            float r0 = __uint_as_float(h << 16);
            float r1 = __uint_as_float(h & 0xffff0000u);
            uint32_t l; PACKBF(l, x0 - r0, x1 - r1);
            *(uint32_t*)(smf + FQ_QHI + qkoff) = h;
            *(uint32_t*)(smf + FQ_QLO + qkoff) = l;
        }
        {
            float x0 = base[4096 + (2*cp) * 256 + row];
            float x1 = base[4096 + (2*cp+1) * 256 + row];
            uint32_t h; PACKBF(h, x0, x1);
            float r0 = __uint_as_float(h << 16);
            float r1 = __uint_as_float(h & 0xffff0000u);
            uint32_t l; PACKBF(l, x0 - r0, x1 - r1);
            *(uint32_t*)(smf + FQ_KHI + qkoff) = h;
            *(uint32_t*)(smf + FQ_KLO + qkoff) = l;
        }
        {
            float x0 = base[8192 + (2*cp) * 256 + row];
            float x1 = base[8192 + (2*cp+1) * 256 + row];
            uint32_t h; PACKBF(h, x0, x1);
            float r0 = __uint_as_float(h << 16);
            float r1 = __uint_as_float(h & 0xffff0000u);
            uint32_t l; PACKBF(l, x0 - r0, x1 - r1);
            int c0 = 2*cp, c1 = 2*cp + 1, y = row;
            uint32_t o0 = (uint32_t)(c0 * 512 + y * 2) ^ (uint32_t)((c0 & 7) << 4);
            uint32_t o1 = (uint32_t)(c1 * 512 + y * 2) ^ (uint32_t)((c1 & 7) << 4);
            *(uint16_t*)(smf + FQ_VHI + o0) = (uint16_t)(h & 0xffff);
            *(uint16_t*)(smf + FQ_VHI + o1) = (uint16_t)(h >> 16);
            *(uint16_t*)(smf + FQ_VLO + o0) = (uint16_t)(l & 0xffff);
            *(uint16_t*)(smf + FQ_VLO + o1) = (uint16_t)(l >> 16);
        }
    }
    __syncthreads();

    // Q fragments (persistent): 4 m-tiles of warp's 64-f band
    int fw = wid * 64;
    int l16 = lane & 15;
    int kh16 = ((lane >> 4) & 1) << 4;      // byte offset for k-half (c*2)
    uint4 qh[4], ql[4];
    #pragma unroll
    for (int mt = 0; mt < 4; mt++) {
        int fr = fw + mt * 16 + l16;
        uint32_t off = (uint32_t)(fr * 32 + kh16) ^ (uint32_t)(((fr >> 2) & 1) << 4);
        ldmx4(qh[mt], sb + FQ_QHI + off);
        ldmx4(ql[mt], sb + FQ_QLO + off);
    }

    float O[4][2][4];
    #pragma unroll
    for (int mt = 0; mt < 4; mt++)
        #pragma unroll
        for (int nt = 0; nt < 2; nt++)
            #pragma unroll
            for (int j = 0; j < 4; j++) O[mt][nt][j] = 0.f;
    float lsum[8];
    #pragma unroll
    for (int i = 0; i < 8; i++) lsum[i] = 0.f;

    int rlow = l16 & 7;
    int khb = ((l16 >> 3) & 1) << 4;

    for (int y0 = 0; y0 < 256; y0 += 16) {
        uint32_t kb0[2], kb1[2], klb0[2], klb1[2];
        #pragma unroll
        for (int nt = 0; nt < 2; nt++) {
            int kr = y0 + nt * 8 + rlow;
            uint32_t off = (uint32_t)(kr * 32 + khb) ^ (uint32_t)(((kr >> 2) & 1) << 4);
            ldmx2(kb0[nt], kb1[nt], sb + FQ_KHI + off);
            ldmx2(klb0[nt], klb1[nt], sb + FQ_KLO + off);
        }
        float S[4][2][4];
        #pragma unroll
        for (int mt = 0; mt < 4; mt++)
            #pragma unroll
            for (int nt = 0; nt < 2; nt++) {
                #pragma unroll
                for (int j = 0; j < 4; j++) S[mt][nt][j] = 0.f;
                mma16816(S[mt][nt], qh[mt], kb0[nt], kb1[nt]);
                mma16816(S[mt][nt], ql[mt], kb0[nt], kb1[nt]);
                mma16816(S[mt][nt], qh[mt], klb0[nt], klb1[nt]);
            }
        uint4 ph[4], pl[4];
        #pragma unroll
        for (int mt = 0; mt < 4; mt++) {
            float p[2][4];
            #pragma unroll
            for (int nt = 0; nt < 2; nt++)
                #pragma unroll
                for (int j = 0; j < 4; j++) p[nt][j] = ex2f(S[mt][nt][j]);
            lsum[2*mt]   += (p[0][0] + p[0][1]) + (p[1][0] + p[1][1]);
            lsum[2*mt+1] += (p[0][2] + p[0][3]) + (p[1][2] + p[1][3]);
            uint32_t hreg[4], lreg[4];
            #pragma unroll
            for (int q = 0; q < 4; q++) {
                int nt = q >> 1, jo = (q & 1) * 2;
                uint32_t h; PACKBF(h, p[nt][jo], p[nt][jo+1]);
                float r0 = __uint_as_float(h << 16);
                float r1 = __uint_as_float(h & 0xffff0000u);
                uint32_t l; PACKBF(l, p[nt][jo] - r0, p[nt][jo+1] - r1);
                hreg[q] = h; lreg[q] = l;
            }
            ph[mt] = make_uint4(hreg[0], hreg[1], hreg[2], hreg[3]);
            pl[mt] = make_uint4(lreg[0], lreg[1], lreg[2], lreg[3]);
        }
        uint32_t vb0[2], vb1[2], vlb0[2], vlb1[2];
        #pragma unroll
        for (int nt = 0; nt < 2; nt++) {
            int vc = nt * 8 + rlow;
            uint32_t off = (uint32_t)(vc * 512 + y0 * 2 + khb) ^ (uint32_t)((vc & 7) << 4);
            ldmx2(vb0[nt], vb1[nt], sb + FQ_VHI + off);
            ldmx2(vlb0[nt], vlb1[nt], sb + FQ_VLO + off);
        }
        #pragma unroll
        for (int mt = 0; mt < 4; mt++)
            #pragma unroll
            for (int nt = 0; nt < 2; nt++) {
                mma16816(O[mt][nt], ph[mt], vb0[nt], vb1[nt]);
                mma16816(O[mt][nt], pl[mt], vb0[nt], vb1[nt]);
                mma16816(O[mt][nt], ph[mt], vlb0[nt], vlb1[nt]);
            }
    }

    #pragma unroll
    for (int i = 0; i < 8; i++) {
        lsum[i] += __shfl_xor_sync(0xffffffffu, lsum[i], 1);
        lsum[i] += __shfl_xor_sync(0xffffffffu, lsum[i], 2);
    }

    __syncthreads();
    float* st = (float*)smf;   // stage [16c][256f]
    int r = lane >> 2, cq = (lane & 3) * 2;
    #pragma unroll
    for (int mt = 0; mt < 4; mt++) {
        float i0 = 1.f / lsum[2*mt], i1 = 1.f / lsum[2*mt+1];
        int f = fw + mt * 16 + r;
        #pragma unroll
        for (int nt = 0; nt < 2; nt++) {
            int c = nt * 8 + cq;
            st[c * 256 + f]           = O[mt][nt][0] * i0;
            st[(c + 1) * 256 + f]     = O[mt][nt][1] * i0;
            st[c * 256 + f + 8]       = O[mt][nt][2] * i1;
            st[(c + 1) * 256 + f + 8] = O[mt][nt][3] * i1;
        }
    }
    __syncthreads();
    float4* go = (float4*)(g_fout_t + (size_t)(b * TT + t) * DC * FF);
    const float4* s4 = (const float4*)smf;
    for (int i = tid; i < 1024; i += 128) go[i] = s4[i];
}

// ================= transpose 2 =================
__global__ __launch_bounds__(256)
void asa_transpose_fout_kernel()
{
    __shared__ float tile[32][33];
    int z = blockIdx.z;
    int f0 = blockIdx.x * 32, t0 = blockIdx.y * 32;
    int tx = threadIdx.x, ty = threadIdx.y;
    int b = z / 16, c = z % 16;
    #pragma unroll
    for (int k = 0; k < 32; k += 8) {
        int t = t0 + ty + k, f = f0 + tx;
        if (t < TT) tile[ty + k][tx] = g_fout_t[((size_t)(b * TT + t) * DC + c) * FF + f];
    }
    __syncthreads();
    #pragma unroll
    for (int k = 0; k < 32; k += 8) {
        int f = f0 + ty + k, t = t0 + tx;
        if (t < TT) g_fout_f[((size_t)(b * FF + f) * DC + c) * TT + t] = tile[tx][ty + k];
    }
}

// ======= kernel 3: causal time attention, adjacent-row pair per thread =======
__global__ __launch_bounds__(256, 2)
void asa_time_attn_kernel(const float* __restrict__ inp, const float* __restrict__ w_proj,
    const float* __restrict__ g3, const float* __restrict__ b3, const float* __restrict__ m3,
    const float* __restrict__ v3, const float* __restrict__ a3, float* __restrict__ out)
{
    extern __shared__ float sm[];
    float* kt  = sm;
    float* vf  = sm + 6400;
    float* wp  = sm + 12800;
    float* sc3 = sm + 13824;
    float* sh3 = sm + 13888;
    float* al3 = sm + 13952;

    int f = blockIdx.x, b = blockIdx.y;
    int tid = threadIdx.x;
    size_t cbase = (size_t)b * 32 * SP + (size_t)f * TT;
    size_t fbase = (size_t)(b * FF + f) * DC * TT;
    for (int i = tid; i < 1600; i += 256) {
        int c = i / 100, off = (i % 100) * 4;
        *(float4*)(kt + c * TT + off) = *(const float4*)(g_tqk2 + cbase + (size_t)(16 + c) * SP + off);
        ((float4*)vf)[i] = ((const float4*)(g_fout_f + fbase))[i];
    }
    for (int i = tid; i < 1024; i += 256) wp[i] = w_proj[i];
    if (tid < 64) {
        float s = g3[tid] * rsqrtf(v3[tid] + 1e-5f);
        sc3[tid] = s; sh3[tid] = b3[tid] - m3[tid] * s; al3[tid] = a3[tid];
    }
    __syncthreads();
    if (tid >= 200) return;

    int tA = 2 * tid, tB = tA + 1;
    int cB = tB >> 4;
    int limA = tA - (cB << 4);
    int limB = tB - (cB << 4);

    float qA[16], qB[16];
    #pragma unroll
    for (int c = 0; c < 16; c++) {
        float2 qv = *(const float2*)(g_tqk2 + cbase + (size_t)c * SP + tA);
        qA[c] = qv.x * QS; qB[c] = qv.y * QS;
    }

    float lA = 0.f, lB = 0.f, accA[16], accB[16];
    #pragma unroll
    for (int c = 0; c < 16; c++) { accA[c] = 0.f; accB[c] = 0.f; }

    for (int ch = 0; ch <= cB; ch++) {
        int y0 = ch * 16;
        float sA[16], sB[16];
        #pragma unroll
        for (int i = 0; i < 16; i++) { sA[i] = 0.f; sB[i] = 0.f; }
        #pragma unroll 4
        for (int c = 0; c < 16; c++) {
            const float4* kp = (const float4*)(kt + c * TT + y0);
            float qa = qA[c], qb = qB[c];
            #pragma unroll
            for (int j = 0; j < 4; j++) {
                float4 k4 = kp[j];
                sA[4*j+0] = fmaf(qa, k4.x, sA[4*j+0]); sB[4*j+0] = fmaf(qb, k4.x, sB[4*j+0]);
                sA[4*j+1] = fmaf(qa, k4.y, sA[4*j+1]); sB[4*j+1] = fmaf(qb, k4.y, sB[4*j+1]);
                sA[4*j+2] = fmaf(qa, k4.z, sA[4*j+2]); sB[4*j+2] = fmaf(qb, k4.z, sB[4*j+2]);
                sA[4*j+3] = fmaf(qa, k4.w, sA[4*j+3]); sB[4*j+3] = fmaf(qb, k4.w, sB[4*j+3]);
            }
        }
        if (ch == cB) {
            #pragma unroll
            for (int i = 0; i < 16; i++) {
                if (i > limA) sA[i] = -3e38f;
                if (i > limB) sB[i] = -3e38f;
            }
        }
        float pa = 0.f, pb = 0.f;
        #pragma unroll
        for (int i = 0; i < 16; i++) {
            sA[i] = ex2f(sA[i]); pa += sA[i];
            sB[i] = ex2f(sB[i]); pb += sB[i];
        }
        lA += pa; lB += pb;
        #pragma unroll 4
        for (int c = 0; c < 16; c++) {
            const float4* vp = (const float4*)(vf + c * TT + y0);
            float a = accA[c], bb2 = accB[c];
            #pragma unroll
            for (int j = 0; j < 4; j++) {
                float4 v4 = vp[j];
                a   = fmaf(sA[4*j+0], v4.x, a);   bb2 = fmaf(sB[4*j+0], v4.x, bb2);
                a   = fmaf(sA[4*j+1], v4.y, a);   bb2 = fmaf(sB[4*j+1], v4.y, bb2);
                a   = fmaf(sA[4*j+2], v4.z, a);   bb2 = fmaf(sB[4*j+2], v4.z, bb2);
                a   = fmaf(sA[4*j+3], v4.w, a);   bb2 = fmaf(sB[4*j+3], v4.w, bb2);
            }
            accA[c] = a; accB[c] = bb2;
        }
    }

    float invA = 1.f / lA, invB = 1.f / lB;
    float aA[16], aB[16];
    #pragma unroll
    for (int c = 0; c < 16; c++) { aA[c] = accA[c] * invA; aB[c] = accB[c] * invB; }

    size_t obase = (((size_t)b * CC) * FF + f) * TT + tA;
    #pragma unroll 8
    for (int oc = 0; oc < CC; oc++) {
        const float4* wr = (const float4*)(wp + oc * 16);
        float4 w0 = wr[0], w1 = wr[1], w2 = wr[2], w3 = wr[3];
        float rA = 0.f, rB = 0.f;
        rA = fmaf(w0.x, aA[0],  rA); rB = fmaf(w0.x, aB[0],  rB);
        rA = fmaf(w0.y, aA[1],  rA); rB = fmaf(w0.y, aB[1],  rB);
        rA = fmaf(w0.z, aA[2],  rA); rB = fmaf(w0.z, aB[2],  rB);
        rA = fmaf(w0.w, aA[3],  rA); rB = fmaf(w0.w, aB[3],  rB);
        rA = fmaf(w1.x, aA[4],  rA); rB = fmaf(w1.x, aB[4],  rB);
        rA = fmaf(w1.y, aA[5],  rA); rB = fmaf(w1.y, aB[5],  rB);
        rA = fmaf(w1.z, aA[6],  rA); rB = fmaf(w1.z, aB[6],  rB);
        rA = fmaf(w1.w, aA[7],  rA); rB = fmaf(w1.w, aB[7],  rB);
        rA = fmaf(w2.x, aA[8],  rA); rB = fmaf(w2.x, aB[8],  rB);
        rA = fmaf(w2.y, aA[9],  rA); rB = fmaf(w2.y, aB[9],  rB);
        rA = fmaf(w2.z, aA[10], rA); rB = fmaf(w2.z, aB[10], rB);
        rA = fmaf(w2.w, aA[11], rA); rB = fmaf(w2.w, aB[11], rB);
        rA = fmaf(w3.x, aA[12], rA); rB = fmaf(w3.x, aB[12], rB);
        rA = fmaf(w3.y, aA[13], rA); rB = fmaf(w3.y, aB[13], rB);
        rA = fmaf(w3.z, aA[14], rA); rB = fmaf(w3.z, aB[14], rB);
        rA = fmaf(w3.w, aA[15], rA); rB = fmaf(w3.w, aB[15], rB);
        float sc = sc3[oc], sh = sh3[oc], al = al3[oc];
        rA = fmaf(rA, sc, sh); rA = rA > 0.f ? rA : al * rA;
        rB = fmaf(rB, sc, sh); rB = rB > 0.f ? rB : al * rB;
        float2 res = *(const float2*)(inp + obase + (size_t)oc * SP);
        *(float2*)(out + obase + (size_t)oc * SP) = make_float2(rA + res.x, rB + res.y);
    }
}

// ================= launcher =================
extern "C" void kernel_launch(void* const* d_in, const int* in_sizes, int n_in,
                              void* d_out, int out_size)
{
    (void)in_sizes; (void)n_in; (void)out_size;
    const float* inp    = (const float*)d_in[0];
    const float* w_fqkv = (const float*)d_in[2];
    const float* g1 = (const float*)d_in[3];
    const float* b1 = (const float*)d_in[4];
    const float* m1 = (const float*)d_in[5];
    const float* v1 = (const float*)d_in[6];
    const float* a1 = (const float*)d_in[7];
    const float* w_tqk  = (const float*)d_in[8];
    const float* g2 = (const float*)d_in[9];
    const float* b2 = (const float*)d_in[10];
    const float* m2 = (const float*)d_in[11];
    const float* v2 = (const float*)d_in[12];
    const float* a2 = (const float*)d_in[13];
    const float* w_proj = (const float*)d_in[14];
    const float* g3 = (const float*)d_in[15];
    const float* b3 = (const float*)d_in[16];
    const float* m3 = (const float*)d_in[17];
    const float* v3 = (const float*)d_in[18];
    const float* a3 = (const float*)d_in[19];
    float* out = (float*)d_out;

    cudaFuncSetAttribute(asa_time_attn_kernel,
                         cudaFuncAttributeMaxDynamicSharedMemorySize, 14016 * 4);

    asa_prep_kernel<<<3, 256>>>(w_fqkv, w_tqk, g1, b1, m1, v1, a1,
                                g2, b2, m2, v2, a2);
    asa_conv_mma_kernel<<<dim3(1600, BB), 320>>>(inp);
    asa_transpose_qkv_kernel<<<dim3(13, 8, BB * 48), dim3(32, 8)>>>();
    asa_freq_attn_kernel<<<dim3(TT, BB), 128>>>();
    asa_transpose_fout_kernel<<<dim3(8, 13, BB * 16), dim3(32, 8)>>>();
    asa_time_attn_kernel<<<dim3(FF, BB), 256, 14016 * 4>>>(inp, w_proj,
        g3, b3, m3, v3, a3, out);
}

// round 8
// speedup vs baseline: 2.2214x; 1.2499x over previous
#include <cuda_runtime.h>
#include <cuda_bf16.h>
#include <cstdint>
#include <math.h>

#define BB 4
#define CC 64
#define FF 256
#define TT 400
#define DC 16
#define SP (FF*TT)

#define QS 0.36067376022224085f   /* 0.25 * log2(e) */

__device__ __forceinline__ float ex2f(float x) {
    float r; asm("ex2.approx.ftz.f32 %0, %1;" : "=f"(r) : "f"(x)); return r;
}
__device__ __forceinline__ uint32_t smem_u32(const void* p) {
    uint32_t a;
    asm("{ .reg .u64 t; cvta.to.shared.u64 t, %1; cvt.u32.u64 %0, t; }" : "=r"(a) : "l"(p));
    return a;
}
__device__ __forceinline__ void ldmx2(uint32_t& r0, uint32_t& r1, uint32_t a) {
    asm volatile("ldmatrix.sync.aligned.m8n8.x2.shared.b16 {%0,%1}, [%2];"
                 : "=r"(r0), "=r"(r1) : "r"(a));
}
__device__ __forceinline__ void ldmx4(uint4& r, uint32_t a) {
    asm volatile("ldmatrix.sync.aligned.m8n8.x4.shared.b16 {%0,%1,%2,%3}, [%4];"
                 : "=r"(r.x), "=r"(r.y), "=r"(r.z), "=r"(r.w) : "r"(a));
}
__device__ __forceinline__ void mma16816(float* d, uint4 a, uint32_t b0, uint32_t b1) {
    asm volatile("mma.sync.aligned.m16n8k16.row.col.f32.bf16.bf16.f32 "
        "{%0,%1,%2,%3}, {%4,%5,%6,%7}, {%8,%9}, {%0,%1,%2,%3};"
        : "+f"(d[0]), "+f"(d[1]), "+f"(d[2]), "+f"(d[3])
        : "r"(a.x), "r"(a.y), "r"(a.z), "r"(a.w), "r"(b0), "r"(b1));
}
#define PACKBF(r, a, b) asm("cvt.rn.bf16x2.f32 %0, %1, %2;" : "=r"(r) : "f"(b), "f"(a))

// ---------------- scratch ----------------
static __device__ float g_qkvf_t[(size_t)BB*48*FF*TT];
static __device__ float g_qkvf_f[(size_t)BB*TT*48*FF];
static __device__ float g_tqk2 [(size_t)BB*32*FF*TT];
static __device__ float g_fout_t[(size_t)BB*TT*DC*FF];
static __device__ float g_fout_f[(size_t)BB*FF*DC*TT];
static __device__ __align__(16) uint4 g_wafH[640];
static __device__ __align__(16) uint4 g_wafL[640];
static __device__ float g_shift[80];
static __device__ float g_alpha[80];

// greedy-balanced causal tile assignment (costs 82/81/81/81)
static __device__ const int TILE_LUT[4][7] = {
    {24, 17, 16, 9, 8, 1, 0},
    {23, 18, 15, 10, 7, 2, -1},
    {22, 19, 14, 11, 6, 3, -1},
    {21, 20, 13, 12, 5, 4, -1}
};

// ================= kernel 0: prep =================
__global__ __launch_bounds__(256)
void asa_prep_kernel(const float* __restrict__ w_fqkv, const float* __restrict__ w_tqk,
    const float* __restrict__ g1, const float* __restrict__ b1,
    const float* __restrict__ m1, const float* __restrict__ v1, const float* __restrict__ a1,
    const float* __restrict__ g2, const float* __restrict__ b2,
    const float* __restrict__ m2, const float* __restrict__ v2, const float* __restrict__ a2)
{
    int i = blockIdx.x * 256 + threadIdx.x;
    if (i < 640) {
        int lane = i & 31, ks = (i >> 5) & 3, o = i >> 7;
        int r = lane >> 2, cp = (lane & 3) * 2;
        int oc0 = o * 16 + r, k0 = ks * 16 + cp;
        uint32_t hiR[4], loR[4];
        #pragma unroll
        for (int aa = 0; aa < 4; aa++) {
            int oc = oc0 + ((aa & 1) << 3);
            int kk = k0 + ((aa >> 1) << 3);
            float s, w0, w1;
            if (oc < 48) {
                s = g1[oc] * rsqrtf(v1[oc] + 1e-5f);
                w0 = w_fqkv[oc * 64 + kk] * s; w1 = w_fqkv[oc * 64 + kk + 1] * s;
            } else {
                int j = oc - 48;
                s = g2[j] * rsqrtf(v2[j] + 1e-5f);
                w0 = w_tqk[j * 64 + kk] * s; w1 = w_tqk[j * 64 + kk + 1] * s;
            }
            uint32_t h; PACKBF(h, w0, w1);
            float r0 = __uint_as_float(h << 16);
            float r1 = __uint_as_float(h & 0xffff0000u);
            uint32_t l; PACKBF(l, w0 - r0, w1 - r1);
            hiR[aa] = h; loR[aa] = l;
        }
        g_wafH[i] = make_uint4(hiR[0], hiR[1], hiR[2], hiR[3]);
        g_wafL[i] = make_uint4(loR[0], loR[1], loR[2], loR[3]);
    }
    if (i < 80) {
        float ss, sh, al;
        if (i < 48) { ss = g1[i] * rsqrtf(v1[i] + 1e-5f); sh = b1[i] - m1[i] * ss; al = a1[i]; }
        else { int j = i - 48; ss = g2[j] * rsqrtf(v2[j] + 1e-5f); sh = b2[j] - m2[j] * ss; al = a2[j]; }
        g_shift[i] = sh; g_alpha[i] = al;
    }
}

// ================= kernel 1: conv1x1 via mma.sync bf16 =================
__global__ __launch_bounds__(320)
void asa_conv_mma_kernel(const float* __restrict__ inp)
{
    __shared__ __align__(16) char xhi[8192];
    __shared__ __align__(16) char xlo[8192];
    int tid = threadIdx.x, wid = tid >> 5, lane = tid & 31;
    int b = blockIdx.y;
    int n0 = blockIdx.x * 64;
    const float* xb = inp + (size_t)b * CC * SP + n0;

    for (int ch = tid; ch < 512; ch += 320) {
        int sp = ch & 63, kb = ch >> 6;
        float v[8];
        #pragma unroll
        for (int j = 0; j < 8; j++) v[j] = xb[(size_t)(kb * 8 + j) * SP + sp];
        uint32_t hp[4], lp[4];
        #pragma unroll
        for (int j = 0; j < 4; j++) {
            uint32_t h; PACKBF(h, v[2*j], v[2*j+1]);
            float r0 = __uint_as_float(h << 16);
            float r1 = __uint_as_float(h & 0xffff0000u);
            uint32_t l; PACKBF(l, v[2*j] - r0, v[2*j+1] - r1);
            hp[j] = h; lp[j] = l;
        }
        uint32_t off = sp * 128 + ((kb * 16) ^ ((sp & 7) << 4));
        *(uint4*)(xhi + off) = make_uint4(hp[0], hp[1], hp[2], hp[3]);
        *(uint4*)(xlo + off) = make_uint4(lp[0], lp[1], lp[2], lp[3]);
    }
    __syncthreads();

    int octile = wid >> 1, sptile = wid & 1;
    uint32_t shi = smem_u32(xhi), slo = smem_u32(xlo);
    float d[4][4];
    #pragma unroll
    for (int nt = 0; nt < 4; nt++)
        #pragma unroll
        for (int j = 0; j < 4; j++) d[nt][j] = 0.f;

    int ln = lane & 15;
    int sprow_base = sptile * 32 + (ln & 7);
    int khalf = ((ln >> 3) & 1) << 3;

    #pragma unroll
    for (int ks = 0; ks < 4; ks++) {
        uint4 ah = g_wafH[(octile * 4 + ks) * 32 + lane];
        uint4 al = g_wafL[(octile * 4 + ks) * 32 + lane];
        #pragma unroll
        for (int nt = 0; nt < 4; nt++) {
            int spr = sprow_base + nt * 8;
            int ke = ks * 16 + khalf;
            uint32_t aoff = spr * 128 + ((ke * 2) ^ ((spr & 7) << 4));
            uint32_t bh0, bh1, bl0, bl1;
            ldmx2(bh0, bh1, shi + aoff);
            ldmx2(bl0, bl1, slo + aoff);
            mma16816(d[nt], ah, bh0, bh1);
            mma16816(d[nt], al, bh0, bh1);
            mma16816(d[nt], ah, bl0, bl1);
        }
    }

    int r = lane >> 2, cp = (lane & 3) * 2;
    #pragma unroll
    for (int half = 0; half < 2; half++) {
        int oc = octile * 16 + r + half * 8;
        float sh = g_shift[oc], al = g_alpha[oc];
        float* dst;
        if (oc < 48) dst = g_qkvf_t + ((size_t)b * 48 + oc) * SP + n0;
        else         dst = g_tqk2  + ((size_t)b * 32 + (oc - 48)) * SP + n0;
        #pragma unroll
        for (int nt = 0; nt < 4; nt++) {
            float v0 = d[nt][half * 2 + 0] + sh; v0 = v0 > 0.f ? v0 : al * v0;
            float v1 = d[nt][half * 2 + 1] + sh; v1 = v1 > 0.f ? v1 : al * v1;
            int sp = sptile * 32 + nt * 8 + cp;
            *(float2*)(dst + sp) = make_float2(v0, v1);
        }
    }
}

// ================= transpose 1 =================
__global__ __launch_bounds__(256)
void asa_transpose_qkv_kernel()
{
    __shared__ float tile[32][33];
    int z = blockIdx.z;
    int t0 = blockIdx.x * 32, f0 = blockIdx.y * 32;
    int tx = threadIdx.x, ty = threadIdx.y;
    size_t ibase = (size_t)z * FF * TT;
    #pragma unroll
    for (int k = 0; k < 32; k += 8) {
        int t = t0 + tx, f = f0 + ty + k;
        if (t < TT) tile[ty + k][tx] = g_qkvf_t[ibase + (size_t)f * TT + t];
    }
    __syncthreads();
    int b = z / 48, oc = z % 48;
    #pragma unroll
    for (int k = 0; k < 32; k += 8) {
        int t = t0 + ty + k, f = f0 + tx;
        if (t < TT) g_qkvf_f[((size_t)(b * TT + t) * 48 + oc) * FF + f] = tile[tx][ty + k];
    }
}

// ========== kernel 2: frequency attention via mma.sync (flash-style) ==========
#define FQ_QHI 0
#define FQ_QLO 8192
#define FQ_KHI 16384
#define FQ_KLO 24576
#define FQ_VHI 32768
#define FQ_VLO 40960

__global__ __launch_bounds__(128)
void asa_freq_attn_kernel()
{
    __shared__ __align__(16) char smf[49152];
    int tid = threadIdx.x, wid = tid >> 5, lane = tid & 31;
    int t = blockIdx.x, b = blockIdx.y;
    const float* base = g_qkvf_f + (size_t)(b * TT + t) * 48 * FF;
    uint32_t sb = smem_u32(smf);

    for (int it = 0; it < 16; it++) {
        int idx = it * 128 + tid;
        int row = idx & 255;
        int cp = idx >> 8;
        uint32_t qkoff = (uint32_t)(row * 32 + cp * 4) ^ (uint32_t)(((row >> 2) & 1) << 4);
        {
            float x0 = base[(2*cp) * 256 + row] * QS;
            float x1 = base[(2*cp+1) * 256 + row] * QS;
            uint32_t h; PACKBF(h, x0, x1);
            float r0 = __uint_as_float(h << 16);
            float r1 = __uint_as_float(h & 0xffff0000u);
            uint32_t l; PACKBF(l, x0 - r0, x1 - r1);
            *(uint32_t*)(smf + FQ_QHI + qkoff) = h;
            *(uint32_t*)(smf + FQ_QLO + qkoff) = l;
        }
        {
            float x0 = base[4096 + (2*cp) * 256 + row];
            float x1 = base[4096 + (2*cp+1) * 256 + row];
            uint32_t h; PACKBF(h, x0, x1);
            float r0 = __uint_as_float(h << 16);
            float r1 = __uint_as_float(h & 0xffff0000u);
            uint32_t l; PACKBF(l, x0 - r0, x1 - r1);
            *(uint32_t*)(smf + FQ_KHI + qkoff) = h;
            *(uint32_t*)(smf + FQ_KLO + qkoff) = l;
        }
        {
            float x0 = base[8192 + (2*cp) * 256 + row];
            float x1 = base[8192 + (2*cp+1) * 256 + row];
            uint32_t h; PACKBF(h, x0, x1);
            float r0 = __uint_as_float(h << 16);
            float r1 = __uint_as_float(h & 0xffff0000u);
            uint32_t l; PACKBF(l, x0 - r0, x1 - r1);
            int c0 = 2*cp, c1 = 2*cp + 1, y = row;
            uint32_t o0 = (uint32_t)(c0 * 512 + y * 2) ^ (uint32_t)((c0 & 7) << 4);
            uint32_t o1 = (uint32_t)(c1 * 512 + y * 2) ^ (uint32_t)((c1 & 7) << 4);
            *(uint16_t*)(smf + FQ_VHI + o0) = (uint16_t)(h & 0xffff);
            *(uint16_t*)(smf + FQ_VHI + o1) = (uint16_t)(h >> 16);
            *(uint16_t*)(smf + FQ_VLO + o0) = (uint16_t)(l & 0xffff);
            *(uint16_t*)(smf + FQ_VLO + o1) = (uint16_t)(l >> 16);
        }
    }
    __syncthreads();

    int fw = wid * 64;
    int l16 = lane & 15;
    int kh16 = ((lane >> 4) & 1) << 4;
    uint4 qh[4], ql[4];
    #pragma unroll
    for (int mt = 0; mt < 4; mt++) {
        int fr = fw + mt * 16 + l16;
        uint32_t off = (uint32_t)(fr * 32 + kh16) ^ (uint32_t)(((fr >> 2) & 1) << 4);
        ldmx4(qh[mt], sb + FQ_QHI + off);
        ldmx4(ql[mt], sb + FQ_QLO + off);
    }

    float O[4][2][4];
    #pragma unroll
    for (int mt = 0; mt < 4; mt++)
        #pragma unroll
        for (int nt = 0; nt < 2; nt++)
            #pragma unroll
            for (int j = 0; j < 4; j++) O[mt][nt][j] = 0.f;
    float lsum[8];
    #pragma unroll
    for (int i = 0; i < 8; i++) lsum[i] = 0.f;

    int rlow = l16 & 7;
    int khb = ((l16 >> 3) & 1) << 4;

    for (int y0 = 0; y0 < 256; y0 += 16) {
        uint32_t kb0[2], kb1[2], klb0[2], klb1[2];
        #pragma unroll
        for (int nt = 0; nt < 2; nt++) {
            int kr = y0 + nt * 8 + rlow;
            uint32_t off = (uint32_t)(kr * 32 + khb) ^ (uint32_t)(((kr >> 2) & 1) << 4);
            ldmx2(kb0[nt], kb1[nt], sb + FQ_KHI + off);
            ldmx2(klb0[nt], klb1[nt], sb + FQ_KLO + off);
        }
        float S[4][2][4];
        #pragma unroll
        for (int mt = 0; mt < 4; mt++)
            #pragma unroll
            for (int nt = 0; nt < 2; nt++) {
                #pragma unroll
                for (int j = 0; j < 4; j++) S[mt][nt][j] = 0.f;
                mma16816(S[mt][nt], qh[mt], kb0[nt], kb1[nt]);
                mma16816(S[mt][nt], ql[mt], kb0[nt], kb1[nt]);
                mma16816(S[mt][nt], qh[mt], klb0[nt], klb1[nt]);
            }
        uint4 ph[4], pl[4];
        #pragma unroll
        for (int mt = 0; mt < 4; mt++) {
            float p[2][4];
            #pragma unroll
            for (int nt = 0; nt < 2; nt++)
                #pragma unroll
                for (int j = 0; j < 4; j++) p[nt][j] = ex2f(S[mt][nt][j]);
            lsum[2*mt]   += (p[0][0] + p[0][1]) + (p[1][0] + p[1][1]);
            lsum[2*mt+1] += (p[0][2] + p[0][3]) + (p[1][2] + p[1][3]);
            uint32_t hreg[4], lreg[4];
            #pragma unroll
            for (int q = 0; q < 4; q++) {
                int nt = q >> 1, jo = (q & 1) * 2;
                uint32_t h; PACKBF(h, p[nt][jo], p[nt][jo+1]);
                float r0 = __uint_as_float(h << 16);
                float r1 = __uint_as_float(h & 0xffff0000u);
                uint32_t l; PACKBF(l, p[nt][jo] - r0, p[nt][jo+1] - r1);
                hreg[q] = h; lreg[q] = l;
            }
            ph[mt] = make_uint4(hreg[0], hreg[1], hreg[2], hreg[3]);
            pl[mt] = make_uint4(lreg[0], lreg[1], lreg[2], lreg[3]);
        }
        uint32_t vb0[2], vb1[2], vlb0[2], vlb1[2];
        #pragma unroll
        for (int nt = 0; nt < 2; nt++) {
            int vc = nt * 8 + rlow;
            uint32_t off = (uint32_t)(vc * 512 + y0 * 2 + khb) ^ (uint32_t)((vc & 7) << 4);
            ldmx2(vb0[nt], vb1[nt], sb + FQ_VHI + off);
            ldmx2(vlb0[nt], vlb1[nt], sb + FQ_VLO + off);
        }
        #pragma unroll
        for (int mt = 0; mt < 4; mt++)
            #pragma unroll
            for (int nt = 0; nt < 2; nt++) {
                mma16816(O[mt][nt], ph[mt], vb0[nt], vb1[nt]);
                mma16816(O[mt][nt], pl[mt], vb0[nt], vb1[nt]);
                mma16816(O[mt][nt], ph[mt], vlb0[nt], vlb1[nt]);
            }
    }

    #pragma unroll
    for (int i = 0; i < 8; i++) {
        lsum[i] += __shfl_xor_sync(0xffffffffu, lsum[i], 1);
        lsum[i] += __shfl_xor_sync(0xffffffffu, lsum[i], 2);
    }

    __syncthreads();
    float* st = (float*)smf;
    int r = lane >> 2, cq = (lane & 3) * 2;
    #pragma unroll
    for (int mt = 0; mt < 4; mt++) {
        float i0 = 1.f / lsum[2*mt], i1 = 1.f / lsum[2*mt+1];
        int f = fw + mt * 16 + r;
        #pragma unroll
        for (int nt = 0; nt < 2; nt++) {
            int c = nt * 8 + cq;
            st[c * 256 + f]           = O[mt][nt][0] * i0;
            st[(c + 1) * 256 + f]     = O[mt][nt][1] * i0;
            st[c * 256 + f + 8]       = O[mt][nt][2] * i1;
            st[(c + 1) * 256 + f + 8] = O[mt][nt][3] * i1;
        }
    }
    __syncthreads();
    float4* go = (float4*)(g_fout_t + (size_t)(b * TT + t) * DC * FF);
    const float4* s4 = (const float4*)smf;
    for (int i = tid; i < 1024; i += 128) go[i] = s4[i];
}

// ================= transpose 2 =================
__global__ __launch_bounds__(256)
void asa_transpose_fout_kernel()
{
    __shared__ float tile[32][33];
    int z = blockIdx.z;
    int f0 = blockIdx.x * 32, t0 = blockIdx.y * 32;
    int tx = threadIdx.x, ty = threadIdx.y;
    int b = z / 16, c = z % 16;
    #pragma unroll
    for (int k = 0; k < 32; k += 8) {
        int t = t0 + ty + k, f = f0 + tx;
        if (t < TT) tile[ty + k][tx] = g_fout_t[((size_t)(b * TT + t) * DC + c) * FF + f];
    }
    __syncthreads();
    #pragma unroll
    for (int k = 0; k < 32; k += 8) {
        int f = f0 + ty + k, t = t0 + tx;
        if (t < TT) g_fout_f[((size_t)(b * FF + f) * DC + c) * TT + t] = tile[tx][ty + k];
    }
}

// ======= kernel 3: causal time attention via mma.sync + proj epilogue =======
// smem layout (bytes):
#define TQ_QHI 0        /* 400*32 = 12800 */
#define TQ_QLO 12800
#define TQ_KHI 25600
#define TQ_KLO 38400
#define TQ_VHI 51200    /* 16 rows * 816 = 13056 */
#define TQ_VLO 64256
#define TQ_ST  77312    /* 400 rows * 80B = 32000 */
#define TQ_WP  109312   /* 1024 floats */
#define TQ_SC  113408
#define TQ_SH  113664
#define TQ_AL  113920
#define TQ_SMEM 114176

__global__ __launch_bounds__(128, 2)
void asa_time_attn_kernel(const float* __restrict__ inp, const float* __restrict__ w_proj,
    const float* __restrict__ g3, const float* __restrict__ b3, const float* __restrict__ m3,
    const float* __restrict__ v3, const float* __restrict__ a3, float* __restrict__ out)
{
    extern __shared__ char smt[];
    uint32_t sb = smem_u32(smt);
    int tid = threadIdx.x, wid = tid >> 5, lane = tid & 31;
    int f = blockIdx.x, b = blockIdx.y;
    size_t cbase = (size_t)b * 32 * SP + (size_t)f * TT;
    const float* vg = g_fout_f + (size_t)(b * FF + f) * DC * TT;

    // fill Q (scaled), K (rows t, 32B, XOR swizzle); V^T rows c (816B pitch)
    #pragma unroll 1
    for (int it = 0; it < 25; it++) {
        int idx = it * 128 + tid;
        int t = idx % 400;
        int cp = idx / 400;
        uint32_t qkoff = (uint32_t)(t * 32 + cp * 4) ^ (uint32_t)(((t >> 2) & 1) << 4);
        {
            float x0 = g_tqk2[cbase + (size_t)(2*cp) * SP + t] * QS;
            float x1 = g_tqk2[cbase + (size_t)(2*cp+1) * SP + t] * QS;
            uint32_t h; PACKBF(h, x0, x1);
            float r0 = __uint_as_float(h << 16);
            float r1 = __uint_as_float(h & 0xffff0000u);
            uint32_t l; PACKBF(l, x0 - r0, x1 - r1);
            *(uint32_t*)(smt + TQ_QHI + qkoff) = h;
            *(uint32_t*)(smt + TQ_QLO + qkoff) = l;
        }
        {
            float x0 = g_tqk2[cbase + (size_t)(16 + 2*cp) * SP + t];
            float x1 = g_tqk2[cbase + (size_t)(17 + 2*cp) * SP + t];
            uint32_t h; PACKBF(h, x0, x1);
            float r0 = __uint_as_float(h << 16);
            float r1 = __uint_as_float(h & 0xffff0000u);
            uint32_t l; PACKBF(l, x0 - r0, x1 - r1);
            *(uint32_t*)(smt + TQ_KHI + qkoff) = h;
            *(uint32_t*)(smt + TQ_KLO + qkoff) = l;
        }
        {
            float x0 = vg[(size_t)(2*cp) * TT + t];
            float x1 = vg[(size_t)(2*cp+1) * TT + t];
            uint32_t h; PACKBF(h, x0, x1);
            float r0 = __uint_as_float(h << 16);
            float r1 = __uint_as_float(h & 0xffff0000u);
            uint32_t l; PACKBF(l, x0 - r0, x1 - r1);
            uint32_t o0 = (uint32_t)((2*cp) * 816 + t * 2);
            uint32_t o1 = (uint32_t)((2*cp+1) * 816 + t * 2);
            *(uint16_t*)(smt + TQ_VHI + o0) = (uint16_t)(h & 0xffff);
            *(uint16_t*)(smt + TQ_VHI + o1) = (uint16_t)(h >> 16);
            *(uint16_t*)(smt + TQ_VLO + o0) = (uint16_t)(l & 0xffff);
            *(uint16_t*)(smt + TQ_VLO + o1) = (uint16_t)(l >> 16);
        }
    }
    for (int i = tid; i < 1024; i += 128) ((float*)(smt + TQ_WP))[i] = w_proj[i];
    if (tid < 64) {
        float s = g3[tid] * rsqrtf(v3[tid] + 1e-5f);
        ((float*)(smt + TQ_SC))[tid] = s;
        ((float*)(smt + TQ_SH))[tid] = b3[tid] - m3[tid] * s;
        ((float*)(smt + TQ_AL))[tid] = a3[tid];
    }
    __syncthreads();

    int l16 = lane & 15;
    int kh16 = ((lane >> 4) & 1) << 4;
    int rlow = l16 & 7;
    int khb = ((l16 >> 3) & 1) << 4;
    int rq = lane >> 2, cq = (lane & 3) * 2;
    float* st = (float*)(smt + TQ_ST);

    #pragma unroll 1
    for (int k7 = 0; k7 < 7; k7++) {
        int tile = TILE_LUT[wid][k7];
        if (tile < 0) break;

        uint4 qh, ql;
        {
            int fr = tile * 16 + l16;
            uint32_t off = (uint32_t)(fr * 32 + kh16) ^ (uint32_t)(((fr >> 2) & 1) << 4);
            ldmx4(qh, sb + TQ_QHI + off);
            ldmx4(ql, sb + TQ_QLO + off);
        }
        float O[2][4];
        #pragma unroll
        for (int nt = 0; nt < 2; nt++)
            #pragma unroll
            for (int j = 0; j < 4; j++) O[nt][j] = 0.f;
        float ls0 = 0.f, ls1 = 0.f;

        #pragma unroll 1
        for (int ch = 0; ch <= tile; ch++) {
            int y0 = ch * 16;
            uint32_t kb0[2], kb1[2], klb0[2], klb1[2];
            #pragma unroll
            for (int nt = 0; nt < 2; nt++) {
                int kr = y0 + nt * 8 + rlow;
                uint32_t off = (uint32_t)(kr * 32 + khb) ^ (uint32_t)(((kr >> 2) & 1) << 4);
                ldmx2(kb0[nt], kb1[nt], sb + TQ_KHI + off);
                ldmx2(klb0[nt], klb1[nt], sb + TQ_KLO + off);
            }
            float S[2][4];
            #pragma unroll
            for (int nt = 0; nt < 2; nt++) {
                #pragma unroll
                for (int j = 0; j < 4; j++) S[nt][j] = 0.f;
                mma16816(S[nt], qh, kb0[nt], kb1[nt]);
                mma16816(S[nt], ql, kb0[nt], kb1[nt]);
                mma16816(S[nt], qh, klb0[nt], klb1[nt]);
            }
            if (ch == tile) {
                // in-tile causal mask: col > row -> -inf
                #pragma unroll
                for (int nt = 0; nt < 2; nt++) {
                    int c0 = nt * 8 + cq;
                    if (c0     > rq)     S[nt][0] = -3e38f;
                    if (c0 + 1 > rq)     S[nt][1] = -3e38f;
                    if (c0     > rq + 8) S[nt][2] = -3e38f;
                    if (c0 + 1 > rq + 8) S[nt][3] = -3e38f;
                }
            }
            float p[2][4];
            #pragma unroll
            for (int nt = 0; nt < 2; nt++)
                #pragma unroll
                for (int j = 0; j < 4; j++) p[nt][j] = ex2f(S[nt][j]);
            ls0 += (p[0][0] + p[0][1]) + (p[1][0] + p[1][1]);
            ls1 += (p[0][2] + p[0][3]) + (p[1][2] + p[1][3]);
            uint32_t hreg[4], lreg[4];
            #pragma unroll
            for (int q = 0; q < 4; q++) {
                int nt = q >> 1, jo = (q & 1) * 2;
                uint32_t h; PACKBF(h, p[nt][jo], p[nt][jo+1]);
                float r0 = __uint_as_float(h << 16);
                float r1 = __uint_as_float(h & 0xffff0000u);
                uint32_t l; PACKBF(l, p[nt][jo] - r0, p[nt][jo+1] - r1);
                hreg[q] = h; lreg[q] = l;
            }
            uint4 ph = make_uint4(hreg[0], hreg[1], hreg[2], hreg[3]);
            uint4 pl = make_uint4(lreg[0], lreg[1], lreg[2], lreg[3]);

            uint32_t vb0[2], vb1[2], vlb0[2], vlb1[2];
            #pragma unroll
            for (int nt = 0; nt < 2; nt++) {
                int vc = nt * 8 + rlow;
                uint32_t off = (uint32_t)(vc * 816 + y0 * 2 + khb);
                ldmx2(vb0[nt], vb1[nt], sb + TQ_VHI + off);
                ldmx2(vlb0[nt], vlb1[nt], sb + TQ_VLO + off);
            }
            #pragma unroll
            for (int nt = 0; nt < 2; nt++) {
                mma16816(O[nt], ph, vb0[nt], vb1[nt]);
                mma16816(O[nt], pl, vb0[nt], vb1[nt]);
                mma16816(O[nt], ph, vlb0[nt], vlb1[nt]);
            }
        }

        ls0 += __shfl_xor_sync(0xffffffffu, ls0, 1);
        ls0 += __shfl_xor_sync(0xffffffffu, ls0, 2);
        ls1 += __shfl_xor_sync(0xffffffffu, ls1, 1);
        ls1 += __shfl_xor_sync(0xffffffffu, ls1, 2);
        float i0 = 1.f / ls0, i1 = 1.f / ls1;

        int row0 = tile * 16 + rq, row1 = row0 + 8;
        #pragma unroll
        for (int nt = 0; nt < 2; nt++) {
            int c = nt * 8 + cq;
            st[row0 * 20 + c]     = O[nt][0] * i0;
            st[row0 * 20 + c + 1] = O[nt][1] * i0;
            st[row1 * 20 + c]     = O[nt][2] * i1;
            st[row1 * 20 + c + 1] = O[nt][3] * i1;
        }
    }
    __syncthreads();

    // epilogue: projection + BN + PReLU + residual
    const float* wp  = (const float*)(smt + TQ_WP);
    const float* sc3 = (const float*)(smt + TQ_SC);
    const float* sh3 = (const float*)(smt + TQ_SH);
    const float* al3 = (const float*)(smt + TQ_AL);
    #pragma unroll 1
    for (int t = tid; t < 400; t += 128) {
        float a[16];
        const float* sr = st + t * 20;
        #pragma unroll
        for (int c = 0; c < 16; c++) a[c] = sr[c];
        size_t obase = (((size_t)b * CC) * FF + f) * TT + t;
        #pragma unroll 8
        for (int oc = 0; oc < CC; oc++) {
            const float4* wr = (const float4*)(wp + oc * 16);
            float4 w0 = wr[0], w1 = wr[1], w2 = wr[2], w3 = wr[3];
            float r = 0.f;
            r = fmaf(w0.x, a[0],  r); r = fmaf(w0.y, a[1],  r);
            r = fmaf(w0.z, a[2],  r); r = fmaf(w0.w, a[3],  r);
            r = fmaf(w1.x, a[4],  r); r = fmaf(w1.y, a[5],  r);
            r = fmaf(w1.z, a[6],  r); r = fmaf(w1.w, a[7],  r);
            r = fmaf(w2.x, a[8],  r); r = fmaf(w2.y, a[9],  r);
            r = fmaf(w2.z, a[10], r); r = fmaf(w2.w, a[11], r);
            r = fmaf(w3.x, a[12], r); r = fmaf(w3.y, a[13], r);
            r = fmaf(w3.z, a[14], r); r = fmaf(w3.w, a[15], r);
            r = fmaf(r, sc3[oc], sh3[oc]);
            r = r > 0.f ? r : al3[oc] * r;
            out[obase + (size_t)oc * SP] = r + inp[obase + (size_t)oc * SP];
        }
    }
}

// ================= launcher =================
extern "C" void kernel_launch(void* const* d_in, const int* in_sizes, int n_in,
                              void* d_out, int out_size)
{
    (void)in_sizes; (void)n_in; (void)out_size;
    const float* inp    = (const float*)d_in[0];
    const float* w_fqkv = (const float*)d_in[2];
    const float* g1 = (const float*)d_in[3];
    const float* b1 = (const float*)d_in[4];
    const float* m1 = (const float*)d_in[5];
    const float* v1 = (const float*)d_in[6];
    const float* a1 = (const float*)d_in[7];
    const float* w_tqk  = (const float*)d_in[8];
    const float* g2 = (const float*)d_in[9];
    const float* b2 = (const float*)d_in[10];
    const float* m2 = (const float*)d_in[11];
    const float* v2 = (const float*)d_in[12];
    const float* a2 = (const float*)d_in[13];
    const float* w_proj = (const float*)d_in[14];
    const float* g3 = (const float*)d_in[15];
    const float* b3 = (const float*)d_in[16];
    const float* m3 = (const float*)d_in[17];
    const float* v3 = (const float*)d_in[18];
    const float* a3 = (const float*)d_in[19];
    float* out = (float*)d_out;

    cudaFuncSetAttribute(asa_time_attn_kernel,
                         cudaFuncAttributeMaxDynamicSharedMemorySize, TQ_SMEM);

    asa_prep_kernel<<<3, 256>>>(w_fqkv, w_tqk, g1, b1, m1, v1, a1,
                                g2, b2, m2, v2, a2);
    asa_conv_mma_kernel<<<dim3(1600, BB), 320>>>(inp);
    asa_transpose_qkv_kernel<<<dim3(13, 8, BB * 48), dim3(32, 8)>>>();
    asa_freq_attn_kernel<<<dim3(TT, BB), 128>>>();
    asa_transpose_fout_kernel<<<dim3(8, 13, BB * 16), dim3(32, 8)>>>();
    asa_time_attn_kernel<<<dim3(FF, BB), 128, TQ_SMEM>>>(inp, w_proj,
        g3, b3, m3, v3, a3, out);
}

// round 9
// speedup vs baseline: 2.6771x; 1.2051x over previous
#include <cuda_runtime.h>
#include <cuda_bf16.h>
#include <cstdint>
#include <math.h>

#define BB 4
#define CC 64
#define FF 256
#define TT 400
#define DC 16
#define SP (FF*TT)

#define QS 0.36067376022224085f   /* 0.25 * log2(e) */

__device__ __forceinline__ float ex2f(float x) {
    float r; asm("ex2.approx.ftz.f32 %0, %1;" : "=f"(r) : "f"(x)); return r;
}
__device__ __forceinline__ uint32_t smem_u32(const void* p) {
    uint32_t a;
    asm("{ .reg .u64 t; cvta.to.shared.u64 t, %1; cvt.u32.u64 %0, t; }" : "=r"(a) : "l"(p));
    return a;
}
__device__ __forceinline__ void ldmx2(uint32_t& r0, uint32_t& r1, uint32_t a) {
    asm volatile("ldmatrix.sync.aligned.m8n8.x2.shared.b16 {%0,%1}, [%2];"
                 : "=r"(r0), "=r"(r1) : "r"(a));
}
__device__ __forceinline__ void ldmx4(uint4& r, uint32_t a) {
    asm volatile("ldmatrix.sync.aligned.m8n8.x4.shared.b16 {%0,%1,%2,%3}, [%4];"
                 : "=r"(r.x), "=r"(r.y), "=r"(r.z), "=r"(r.w) : "r"(a));
}
__device__ __forceinline__ void mma16816(float* d, uint4 a, uint32_t b0, uint32_t b1) {
    asm volatile("mma.sync.aligned.m16n8k16.row.col.f32.bf16.bf16.f32 "
        "{%0,%1,%2,%3}, {%4,%5,%6,%7}, {%8,%9}, {%0,%1,%2,%3};"
        : "+f"(d[0]), "+f"(d[1]), "+f"(d[2]), "+f"(d[3])
        : "r"(a.x), "r"(a.y), "r"(a.z), "r"(a.w), "r"(b0), "r"(b1));
}
#define PACKBF(r, a, b) asm("cvt.rn.bf16x2.f32 %0, %1, %2;" : "=r"(r) : "f"(b), "f"(a))

// ---------------- scratch ----------------
static __device__ float g_qkvf_t[(size_t)BB*48*FF*TT];
static __device__ float g_qkvf_f[(size_t)BB*TT*48*FF];
static __device__ float g_tqk2 [(size_t)BB*32*FF*TT];
static __device__ float g_fout_t[(size_t)BB*TT*DC*FF];
static __device__ float g_fout_f[(size_t)BB*FF*DC*TT];
static __device__ __align__(16) uint4 g_wafH[640];
static __device__ __align__(16) uint4 g_wafL[640];
static __device__ float g_shift[80];
static __device__ float g_alpha[80];

// greedy-balanced causal tile assignment over 8 warps (chunk loads 38-44)
static __device__ const int TILE_LUT8[8][8] = {
    {24, 14, 0, -1, -1, -1, -1, -1},
    {23, 15, -1, -1, -1, -1, -1, -1},
    {22, 16, -1, -1, -1, -1, -1, -1},
    {21, 17, -1, -1, -1, -1, -1, -1},
    {20, 18, -1, -1, -1, -1, -1, -1},
    {19, 13, 6, -1, -1, -1, -1, -1},
    {12, 11, 10, 4, -1, -1, -1, -1},
    {9, 8, 7, 5, 3, 2, 1, -1}
};

// ================= kernel 0: prep =================
__global__ __launch_bounds__(256)
void asa_prep_kernel(const float* __restrict__ w_fqkv, const float* __restrict__ w_tqk,
    const float* __restrict__ g1, const float* __restrict__ b1,
    const float* __restrict__ m1, const float* __restrict__ v1, const float* __restrict__ a1,
    const float* __restrict__ g2, const float* __restrict__ b2,
    const float* __restrict__ m2, const float* __restrict__ v2, const float* __restrict__ a2)
{
    int i = blockIdx.x * 256 + threadIdx.x;
    if (i < 640) {
        int lane = i & 31, ks = (i >> 5) & 3, o = i >> 7;
        int r = lane >> 2, cp = (lane & 3) * 2;
        int oc0 = o * 16 + r, k0 = ks * 16 + cp;
        uint32_t hiR[4], loR[4];
        #pragma unroll
        for (int aa = 0; aa < 4; aa++) {
            int oc = oc0 + ((aa & 1) << 3);
            int kk = k0 + ((aa >> 1) << 3);
            float s, w0, w1;
            if (oc < 48) {
                s = g1[oc] * rsqrtf(v1[oc] + 1e-5f);
                w0 = w_fqkv[oc * 64 + kk] * s; w1 = w_fqkv[oc * 64 + kk + 1] * s;
            } else {
                int j = oc - 48;
                s = g2[j] * rsqrtf(v2[j] + 1e-5f);
                w0 = w_tqk[j * 64 + kk] * s; w1 = w_tqk[j * 64 + kk + 1] * s;
            }
            uint32_t h; PACKBF(h, w0, w1);
            float r0 = __uint_as_float(h << 16);
            float r1 = __uint_as_float(h & 0xffff0000u);
            uint32_t l; PACKBF(l, w0 - r0, w1 - r1);
            hiR[aa] = h; loR[aa] = l;
        }
        g_wafH[i] = make_uint4(hiR[0], hiR[1], hiR[2], hiR[3]);
        g_wafL[i] = make_uint4(loR[0], loR[1], loR[2], loR[3]);
    }
    if (i < 80) {
        float ss, sh, al;
        if (i < 48) { ss = g1[i] * rsqrtf(v1[i] + 1e-5f); sh = b1[i] - m1[i] * ss; al = a1[i]; }
        else { int j = i - 48; ss = g2[j] * rsqrtf(v2[j] + 1e-5f); sh = b2[j] - m2[j] * ss; al = a2[j]; }
        g_shift[i] = sh; g_alpha[i] = al;
    }
}

// ====== kernel 1: conv1x1 via mma.sync bf16 — float4 loads + smem staging ======
__global__ __launch_bounds__(320)
void asa_conv_mma_kernel(const float* __restrict__ inp)
{
    __shared__ __align__(16) float xstage[64 * 68];   // pitch 68 to dodge bank conflicts
    __shared__ __align__(16) char xhi[8192];
    __shared__ __align__(16) char xlo[8192];
    int tid = threadIdx.x, wid = tid >> 5, lane = tid & 31;
    int b = blockIdx.y;
    int n0 = blockIdx.x * 64;
    const float* xb = inp + (size_t)b * CC * SP + n0;

    // phase 1: coalesced float4 loads -> f32 staging [k][sp]
    for (int i = tid; i < 1024; i += 320) {
        int k = i >> 4, s4 = (i & 15) * 4;
        float4 v = *(const float4*)(xb + (size_t)k * SP + s4);
        *(float4*)(xstage + k * 68 + s4) = v;
    }
    __syncthreads();

    // phase 2: transpose from staging, split hi/lo, swizzled K-major rows [sp][k]
    for (int ch = tid; ch < 512; ch += 320) {
        int sp = ch & 63, kb = ch >> 6;
        float v[8];
        #pragma unroll
        for (int j = 0; j < 8; j++) v[j] = xstage[(kb * 8 + j) * 68 + sp];
        uint32_t hp[4], lp[4];
        #pragma unroll
        for (int j = 0; j < 4; j++) {
            uint32_t h; PACKBF(h, v[2*j], v[2*j+1]);
            float r0 = __uint_as_float(h << 16);
            float r1 = __uint_as_float(h & 0xffff0000u);
            uint32_t l; PACKBF(l, v[2*j] - r0, v[2*j+1] - r1);
            hp[j] = h; lp[j] = l;
        }
        uint32_t off = sp * 128 + ((kb * 16) ^ ((sp & 7) << 4));
        *(uint4*)(xhi + off) = make_uint4(hp[0], hp[1], hp[2], hp[3]);
        *(uint4*)(xlo + off) = make_uint4(lp[0], lp[1], lp[2], lp[3]);
    }
    __syncthreads();

    int octile = wid >> 1, sptile = wid & 1;
    uint32_t shi = smem_u32(xhi), slo = smem_u32(xlo);
    float d[4][4];
    #pragma unroll
    for (int nt = 0; nt < 4; nt++)
        #pragma unroll
        for (int j = 0; j < 4; j++) d[nt][j] = 0.f;

    int ln = lane & 15;
    int sprow_base = sptile * 32 + (ln & 7);
    int khalf = ((ln >> 3) & 1) << 3;

    #pragma unroll
    for (int ks = 0; ks < 4; ks++) {
        uint4 ah = g_wafH[(octile * 4 + ks) * 32 + lane];
        uint4 al = g_wafL[(octile * 4 + ks) * 32 + lane];
        #pragma unroll
        for (int nt = 0; nt < 4; nt++) {
            int spr = sprow_base + nt * 8;
            int ke = ks * 16 + khalf;
            uint32_t aoff = spr * 128 + ((ke * 2) ^ ((spr & 7) << 4));
            uint32_t bh0, bh1, bl0, bl1;
            ldmx2(bh0, bh1, shi + aoff);
            ldmx2(bl0, bl1, slo + aoff);
            mma16816(d[nt], ah, bh0, bh1);
            mma16816(d[nt], al, bh0, bh1);
            mma16816(d[nt], ah, bl0, bl1);
        }
    }

    int r = lane >> 2, cp = (lane & 3) * 2;
    #pragma unroll
    for (int half = 0; half < 2; half++) {
        int oc = octile * 16 + r + half * 8;
        float sh = g_shift[oc], al = g_alpha[oc];
        float* dst;
        if (oc < 48) dst = g_qkvf_t + ((size_t)b * 48 + oc) * SP + n0;
        else         dst = g_tqk2  + ((size_t)b * 32 + (oc - 48)) * SP + n0;
        #pragma unroll
        for (int nt = 0; nt < 4; nt++) {
            float v0 = d[nt][half * 2 + 0] + sh; v0 = v0 > 0.f ? v0 : al * v0;
            float v1 = d[nt][half * 2 + 1] + sh; v1 = v1 > 0.f ? v1 : al * v1;
            int sp = sptile * 32 + nt * 8 + cp;
            *(float2*)(dst + sp) = make_float2(v0, v1);
        }
    }
}

// ================= transpose 1 =================
__global__ __launch_bounds__(256)
void asa_transpose_qkv_kernel()
{
    __shared__ float tile[32][33];
    int z = blockIdx.z;
    int t0 = blockIdx.x * 32, f0 = blockIdx.y * 32;
    int tx = threadIdx.x, ty = threadIdx.y;
    size_t ibase = (size_t)z * FF * TT;
    #pragma unroll
    for (int k = 0; k < 32; k += 8) {
        int t = t0 + tx, f = f0 + ty + k;
        if (t < TT) tile[ty + k][tx] = g_qkvf_t[ibase + (size_t)f * TT + t];
    }
    __syncthreads();
    int b = z / 48, oc = z % 48;
    #pragma unroll
    for (int k = 0; k < 32; k += 8) {
        int t = t0 + ty + k, f = f0 + tx;
        if (t < TT) g_qkvf_f[((size_t)(b * TT + t) * 48 + oc) * FF + f] = tile[tx][ty + k];
    }
}

// ========== kernel 2: frequency attention via mma.sync (flash-style) ==========
#define FQ_QHI 0
#define FQ_QLO 8192
#define FQ_KHI 16384
#define FQ_KLO 24576
#define FQ_VHI 32768
#define FQ_VLO 40960

__global__ __launch_bounds__(128)
void asa_freq_attn_kernel()
{
    __shared__ __align__(16) char smf[49152];
    int tid = threadIdx.x, wid = tid >> 5, lane = tid & 31;
    int t = blockIdx.x, b = blockIdx.y;
    const float* base = g_qkvf_f + (size_t)(b * TT + t) * 48 * FF;
    uint32_t sb = smem_u32(smf);

    for (int it = 0; it < 16; it++) {
        int idx = it * 128 + tid;
        int row = idx & 255;
        int cp = idx >> 8;
        uint32_t qkoff = (uint32_t)(row * 32 + cp * 4) ^ (uint32_t)(((row >> 2) & 1) << 4);
        {
            float x0 = base[(2*cp) * 256 + row] * QS;
            float x1 = base[(2*cp+1) * 256 + row] * QS;
            uint32_t h; PACKBF(h, x0, x1);
            float r0 = __uint_as_float(h << 16);
            float r1 = __uint_as_float(h & 0xffff0000u);
            uint32_t l; PACKBF(l, x0 - r0, x1 - r1);
            *(uint32_t*)(smf + FQ_QHI + qkoff) = h;
            *(uint32_t*)(smf + FQ_QLO + qkoff) = l;
        }
        {
            float x0 = base[4096 + (2*cp) * 256 + row];
            float x1 = base[4096 + (2*cp+1) * 256 + row];
            uint32_t h; PACKBF(h, x0, x1);
            float r0 = __uint_as_float(h << 16);
            float r1 = __uint_as_float(h & 0xffff0000u);
            uint32_t l; PACKBF(l, x0 - r0, x1 - r1);
            *(uint32_t*)(smf + FQ_KHI + qkoff) = h;
            *(uint32_t*)(smf + FQ_KLO + qkoff) = l;
        }
        {
            float x0 = base[8192 + (2*cp) * 256 + row];
            float x1 = base[8192 + (2*cp+1) * 256 + row];
            uint32_t h; PACKBF(h, x0, x1);
            float r0 = __uint_as_float(h << 16);
            float r1 = __uint_as_float(h & 0xffff0000u);
            uint32_t l; PACKBF(l, x0 - r0, x1 - r1);
            int c0 = 2*cp, c1 = 2*cp + 1, y = row;
            uint32_t o0 = (uint32_t)(c0 * 512 + y * 2) ^ (uint32_t)((c0 & 7) << 4);
            uint32_t o1 = (uint32_t)(c1 * 512 + y * 2) ^ (uint32_t)((c1 & 7) << 4);
            *(uint16_t*)(smf + FQ_VHI + o0) = (uint16_t)(h & 0xffff);
            *(uint16_t*)(smf + FQ_VHI + o1) = (uint16_t)(h >> 16);
            *(uint16_t*)(smf + FQ_VLO + o0) = (uint16_t)(l & 0xffff);
            *(uint16_t*)(smf + FQ_VLO + o1) = (uint16_t)(l >> 16);
        }
    }
    __syncthreads();

    int fw = wid * 64;
    int l16 = lane & 15;
    int kh16 = ((lane >> 4) & 1) << 4;
    uint4 qh[4], ql[4];
    #pragma unroll
    for (int mt = 0; mt < 4; mt++) {
        int fr = fw + mt * 16 + l16;
        uint32_t off = (uint32_t)(fr * 32 + kh16) ^ (uint32_t)(((fr >> 2) & 1) << 4);
        ldmx4(qh[mt], sb + FQ_QHI + off);
        ldmx4(ql[mt], sb + FQ_QLO + off);
    }

    float O[4][2][4];
    #pragma unroll
    for (int mt = 0; mt < 4; mt++)
        #pragma unroll
        for (int nt = 0; nt < 2; nt++)
            #pragma unroll
            for (int j = 0; j < 4; j++) O[mt][nt][j] = 0.f;
    float lsum[8];
    #pragma unroll
    for (int i = 0; i < 8; i++) lsum[i] = 0.f;

    int rlow = l16 & 7;
    int khb = ((l16 >> 3) & 1) << 4;

    for (int y0 = 0; y0 < 256; y0 += 16) {
        uint32_t kb0[2], kb1[2], klb0[2], klb1[2];
        #pragma unroll
        for (int nt = 0; nt < 2; nt++) {
            int kr = y0 + nt * 8 + rlow;
            uint32_t off = (uint32_t)(kr * 32 + khb) ^ (uint32_t)(((kr >> 2) & 1) << 4);
            ldmx2(kb0[nt], kb1[nt], sb + FQ_KHI + off);
            ldmx2(klb0[nt], klb1[nt], sb + FQ_KLO + off);
        }
        float S[4][2][4];
        #pragma unroll
        for (int mt = 0; mt < 4; mt++)
            #pragma unroll
            for (int nt = 0; nt < 2; nt++) {
                #pragma unroll
                for (int j = 0; j < 4; j++) S[mt][nt][j] = 0.f;
                mma16816(S[mt][nt], qh[mt], kb0[nt], kb1[nt]);
                mma16816(S[mt][nt], ql[mt], kb0[nt], kb1[nt]);
                mma16816(S[mt][nt], qh[mt], klb0[nt], klb1[nt]);
            }
        uint4 ph[4], pl[4];
        #pragma unroll
        for (int mt = 0; mt < 4; mt++) {
            float p[2][4];
            #pragma unroll
            for (int nt = 0; nt < 2; nt++)
                #pragma unroll
                for (int j = 0; j < 4; j++) p[nt][j] = ex2f(S[mt][nt][j]);
            lsum[2*mt]   += (p[0][0] + p[0][1]) + (p[1][0] + p[1][1]);
            lsum[2*mt+1] += (p[0][2] + p[0][3]) + (p[1][2] + p[1][3]);
            uint32_t hreg[4], lreg[4];
            #pragma unroll
            for (int q = 0; q < 4; q++) {
                int nt = q >> 1, jo = (q & 1) * 2;
                uint32_t h; PACKBF(h, p[nt][jo], p[nt][jo+1]);
                float r0 = __uint_as_float(h << 16);
                float r1 = __uint_as_float(h & 0xffff0000u);
                uint32_t l; PACKBF(l, p[nt][jo] - r0, p[nt][jo+1] - r1);
                hreg[q] = h; lreg[q] = l;
            }
            ph[mt] = make_uint4(hreg[0], hreg[1], hreg[2], hreg[3]);
            pl[mt] = make_uint4(lreg[0], lreg[1], lreg[2], lreg[3]);
        }
        uint32_t vb0[2], vb1[2], vlb0[2], vlb1[2];
        #pragma unroll
        for (int nt = 0; nt < 2; nt++) {
            int vc = nt * 8 + rlow;
            uint32_t off = (uint32_t)(vc * 512 + y0 * 2 + khb) ^ (uint32_t)((vc & 7) << 4);
            ldmx2(vb0[nt], vb1[nt], sb + FQ_VHI + off);
            ldmx2(vlb0[nt], vlb1[nt], sb + FQ_VLO + off);
        }
        #pragma unroll
        for (int mt = 0; mt < 4; mt++)
            #pragma unroll
            for (int nt = 0; nt < 2; nt++) {
                mma16816(O[mt][nt], ph[mt], vb0[nt], vb1[nt]);
                mma16816(O[mt][nt], pl[mt], vb0[nt], vb1[nt]);
                mma16816(O[mt][nt], ph[mt], vlb0[nt], vlb1[nt]);
            }
    }

    #pragma unroll
    for (int i = 0; i < 8; i++) {
        lsum[i] += __shfl_xor_sync(0xffffffffu, lsum[i], 1);
        lsum[i] += __shfl_xor_sync(0xffffffffu, lsum[i], 2);
    }

    __syncthreads();
    float* st = (float*)smf;
    int r = lane >> 2, cq = (lane & 3) * 2;
    #pragma unroll
    for (int mt = 0; mt < 4; mt++) {
        float i0 = 1.f / lsum[2*mt], i1 = 1.f / lsum[2*mt+1];
        int f = fw + mt * 16 + r;
        #pragma unroll
        for (int nt = 0; nt < 2; nt++) {
            int c = nt * 8 + cq;
            st[c * 256 + f]           = O[mt][nt][0] * i0;
            st[(c + 1) * 256 + f]     = O[mt][nt][1] * i0;
            st[c * 256 + f + 8]       = O[mt][nt][2] * i1;
            st[(c + 1) * 256 + f + 8] = O[mt][nt][3] * i1;
        }
    }
    __syncthreads();
    float4* go = (float4*)(g_fout_t + (size_t)(b * TT + t) * DC * FF);
    const float4* s4 = (const float4*)smf;
    for (int i = tid; i < 1024; i += 128) go[i] = s4[i];
}

// ================= transpose 2 =================
__global__ __launch_bounds__(256)
void asa_transpose_fout_kernel()
{
    __shared__ float tile[32][33];
    int z = blockIdx.z;
    int f0 = blockIdx.x * 32, t0 = blockIdx.y * 32;
    int tx = threadIdx.x, ty = threadIdx.y;
    int b = z / 16, c = z % 16;
    #pragma unroll
    for (int k = 0; k < 32; k += 8) {
        int t = t0 + ty + k, f = f0 + tx;
        if (t < TT) tile[ty + k][tx] = g_fout_t[((size_t)(b * TT + t) * DC + c) * FF + f];
    }
    __syncthreads();
    #pragma unroll
    for (int k = 0; k < 32; k += 8) {
        int f = f0 + ty + k, t = t0 + tx;
        if (t < TT) g_fout_f[((size_t)(b * FF + f) * DC + c) * TT + t] = tile[tx][ty + k];
    }
}

// ======= kernel 3: causal time attention via mma.sync, 8 warps =======
#define TQ_QHI 0        /* 400*32 = 12800 */
#define TQ_QLO 12800
#define TQ_KHI 25600
#define TQ_KLO 38400
#define TQ_VHI 51200    /* 16 rows * 816 = 13056 */
#define TQ_VLO 64256
#define TQ_ST  77312    /* 400 rows * 80B = 32000 */
#define TQ_WP  109312
#define TQ_SC  113408
#define TQ_SH  113664
#define TQ_AL  113920
#define TQ_SMEM 114176

__global__ __launch_bounds__(256, 2)
void asa_time_attn_kernel(const float* __restrict__ inp, const float* __restrict__ w_proj,
    const float* __restrict__ g3, const float* __restrict__ b3, const float* __restrict__ m3,
    const float* __restrict__ v3, const float* __restrict__ a3, float* __restrict__ out)
{
    extern __shared__ char smt[];
    uint32_t sb = smem_u32(smt);
    int tid = threadIdx.x, wid = tid >> 5, lane = tid & 31;
    int f = blockIdx.x, b = blockIdx.y;
    size_t cbase = (size_t)b * 32 * SP + (size_t)f * TT;
    const float* vg = g_fout_f + (size_t)(b * FF + f) * DC * TT;

    #pragma unroll 1
    for (int idx = tid; idx < 3200; idx += 256) {
        int t = idx % 400;
        int cp = idx / 400;
        uint32_t qkoff = (uint32_t)(t * 32 + cp * 4) ^ (uint32_t)(((t >> 2) & 1) << 4);
        {
            float x0 = g_tqk2[cbase + (size_t)(2*cp) * SP + t] * QS;
            float x1 = g_tqk2[cbase + (size_t)(2*cp+1) * SP + t] * QS;
            uint32_t h; PACKBF(h, x0, x1);
            float r0 = __uint_as_float(h << 16);
            float r1 = __uint_as_float(h & 0xffff0000u);
            uint32_t l; PACKBF(l, x0 - r0, x1 - r1);
            *(uint32_t*)(smt + TQ_QHI + qkoff) = h;
            *(uint32_t*)(smt + TQ_QLO + qkoff) = l;
        }
        {
            float x0 = g_tqk2[cbase + (size_t)(16 + 2*cp) * SP + t];
            float x1 = g_tqk2[cbase + (size_t)(17 + 2*cp) * SP + t];
            uint32_t h; PACKBF(h, x0, x1);
            float r0 = __uint_as_float(h << 16);
            float r1 = __uint_as_float(h & 0xffff0000u);
            uint32_t l; PACKBF(l, x0 - r0, x1 - r1);
            *(uint32_t*)(smt + TQ_KHI + qkoff) = h;
            *(uint32_t*)(smt + TQ_KLO + qkoff) = l;
        }
        {
            float x0 = vg[(size_t)(2*cp) * TT + t];
            float x1 = vg[(size_t)(2*cp+1) * TT + t];
            uint32_t h; PACKBF(h, x0, x1);
            float r0 = __uint_as_float(h << 16);
            float r1 = __uint_as_float(h & 0xffff0000u);
            uint32_t l; PACKBF(l, x0 - r0, x1 - r1);
            uint32_t o0 = (uint32_t)((2*cp) * 816 + t * 2);
            uint32_t o1 = (uint32_t)((2*cp+1) * 816 + t * 2);
            *(uint16_t*)(smt + TQ_VHI + o0) = (uint16_t)(h & 0xffff);
            *(uint16_t*)(smt + TQ_VHI + o1) = (uint16_t)(h >> 16);
            *(uint16_t*)(smt + TQ_VLO + o0) = (uint16_t)(l & 0xffff);
            *(uint16_t*)(smt + TQ_VLO + o1) = (uint16_t)(l >> 16);
        }
    }
    for (int i = tid; i < 1024; i += 256) ((float*)(smt + TQ_WP))[i] = w_proj[i];
    if (tid < 64) {
        float s = g3[tid] * rsqrtf(v3[tid] + 1e-5f);
        ((float*)(smt + TQ_SC))[tid] = s;
        ((float*)(smt + TQ_SH))[tid] = b3[tid] - m3[tid] * s;
        ((float*)(smt + TQ_AL))[tid] = a3[tid];
    }
    __syncthreads();

    int l16 = lane & 15;
    int kh16 = ((lane >> 4) & 1) << 4;
    int rlow = l16 & 7;
    int khb = ((l16 >> 3) & 1) << 4;
    int rq = lane >> 2, cq = (lane & 3) * 2;
    float* st = (float*)(smt + TQ_ST);

    #pragma unroll 1
    for (int k8 = 0; k8 < 8; k8++) {
        int tile = TILE_LUT8[wid][k8];
        if (tile < 0) break;

        uint4 qh, ql;
        {
            int fr = tile * 16 + l16;
            uint32_t off = (uint32_t)(fr * 32 + kh16) ^ (uint32_t)(((fr >> 2) & 1) << 4);
            ldmx4(qh, sb + TQ_QHI + off);
            ldmx4(ql, sb + TQ_QLO + off);
        }
        float O[2][4];
        #pragma unroll
        for (int nt = 0; nt < 2; nt++)
            #pragma unroll
            for (int j = 0; j < 4; j++) O[nt][j] = 0.f;
        float ls0 = 0.f, ls1 = 0.f;

        #pragma unroll 1
        for (int ch = 0; ch <= tile; ch++) {
            int y0 = ch * 16;
            uint32_t kb0[2], kb1[2], klb0[2], klb1[2];
            #pragma unroll
            for (int nt = 0; nt < 2; nt++) {
                int kr = y0 + nt * 8 + rlow;
                uint32_t off = (uint32_t)(kr * 32 + khb) ^ (uint32_t)(((kr >> 2) & 1) << 4);
                ldmx2(kb0[nt], kb1[nt], sb + TQ_KHI + off);
                ldmx2(klb0[nt], klb1[nt], sb + TQ_KLO + off);
            }
            float S[2][4];
            #pragma unroll
            for (int nt = 0; nt < 2; nt++) {
                #pragma unroll
                for (int j = 0; j < 4; j++) S[nt][j] = 0.f;
                mma16816(S[nt], qh, kb0[nt], kb1[nt]);
                mma16816(S[nt], ql, kb0[nt], kb1[nt]);
                mma16816(S[nt], qh, klb0[nt], klb1[nt]);
            }
            if (ch == tile) {
                #pragma unroll
                for (int nt = 0; nt < 2; nt++) {
                    int c0 = nt * 8 + cq;
                    if (c0     > rq)     S[nt][0] = -3e38f;
                    if (c0 + 1 > rq)     S[nt][1] = -3e38f;
                    if (c0     > rq + 8) S[nt][2] = -3e38f;
                    if (c0 + 1 > rq + 8) S[nt][3] = -3e38f;
                }
            }
            float p[2][4];
            #pragma unroll
            for (int nt = 0; nt < 2; nt++)
                #pragma unroll
                for (int j = 0; j < 4; j++) p[nt][j] = ex2f(S[nt][j]);
            ls0 += (p[0][0] + p[0][1]) + (p[1][0] + p[1][1]);
            ls1 += (p[0][2] + p[0][3]) + (p[1][2] + p[1][3]);
            uint32_t hreg[4], lreg[4];
            #pragma unroll
            for (int q = 0; q < 4; q++) {
                int nt = q >> 1, jo = (q & 1) * 2;
                uint32_t h; PACKBF(h, p[nt][jo], p[nt][jo+1]);
                float r0 = __uint_as_float(h << 16);
                float r1 = __uint_as_float(h & 0xffff0000u);
                uint32_t l; PACKBF(l, p[nt][jo] - r0, p[nt][jo+1] - r1);
                hreg[q] = h; lreg[q] = l;
            }
            uint4 ph = make_uint4(hreg[0], hreg[1], hreg[2], hreg[3]);
            uint4 pl = make_uint4(lreg[0], lreg[1], lreg[2], lreg[3]);

            uint32_t vb0[2], vb1[2], vlb0[2], vlb1[2];
            #pragma unroll
            for (int nt = 0; nt < 2; nt++) {
                int vc = nt * 8 + rlow;
                uint32_t off = (uint32_t)(vc * 816 + y0 * 2 + khb);
                ldmx2(vb0[nt], vb1[nt], sb + TQ_VHI + off);
                ldmx2(vlb0[nt], vlb1[nt], sb + TQ_VLO + off);
            }
            #pragma unroll
            for (int nt = 0; nt < 2; nt++) {
                mma16816(O[nt], ph, vb0[nt], vb1[nt]);
                mma16816(O[nt], pl, vb0[nt], vb1[nt]);
                mma16816(O[nt], ph, vlb0[nt], vlb1[nt]);
            }
        }

        ls0 += __shfl_xor_sync(0xffffffffu, ls0, 1);
        ls0 += __shfl_xor_sync(0xffffffffu, ls0, 2);
        ls1 += __shfl_xor_sync(0xffffffffu, ls1, 1);
        ls1 += __shfl_xor_sync(0xffffffffu, ls1, 2);
        float i0 = 1.f / ls0, i1 = 1.f / ls1;

        int row0 = tile * 16 + rq, row1 = row0 + 8;
        #pragma unroll
        for (int nt = 0; nt < 2; nt++) {
            int c = nt * 8 + cq;
            st[row0 * 20 + c]     = O[nt][0] * i0;
            st[row0 * 20 + c + 1] = O[nt][1] * i0;
            st[row1 * 20 + c]     = O[nt][2] * i1;
            st[row1 * 20 + c + 1] = O[nt][3] * i1;
        }
    }
    __syncthreads();

    const float* wp  = (const float*)(smt + TQ_WP);
    const float* sc3 = (const float*)(smt + TQ_SC);
    const float* sh3 = (const float*)(smt + TQ_SH);
    const float* al3 = (const float*)(smt + TQ_AL);
    #pragma unroll 1
    for (int t = tid; t < 400; t += 256) {
        float a[16];
        const float* sr = st + t * 20;
        #pragma unroll
        for (int c = 0; c < 16; c++) a[c] = sr[c];
        size_t obase = (((size_t)b * CC) * FF + f) * TT + t;
        #pragma unroll 8
        for (int oc = 0; oc < CC; oc++) {
            const float4* wr = (const float4*)(wp + oc * 16);
            float4 w0 = wr[0], w1 = wr[1], w2 = wr[2], w3 = wr[3];
            float r = 0.f;
            r = fmaf(w0.x, a[0],  r); r = fmaf(w0.y, a[1],  r);
            r = fmaf(w0.z, a[2],  r); r = fmaf(w0.w, a[3],  r);
            r = fmaf(w1.x, a[4],  r); r = fmaf(w1.y, a[5],  r);
            r = fmaf(w1.z, a[6],  r); r = fmaf(w1.w, a[7],  r);
            r = fmaf(w2.x, a[8],  r); r = fmaf(w2.y, a[9],  r);
            r = fmaf(w2.z, a[10], r); r = fmaf(w2.w, a[11], r);
            r = fmaf(w3.x, a[12], r); r = fmaf(w3.y, a[13], r);
            r = fmaf(w3.z, a[14], r); r = fmaf(w3.w, a[15], r);
            r = fmaf(r, sc3[oc], sh3[oc]);
            r = r > 0.f ? r : al3[oc] * r;
            out[obase + (size_t)oc * SP] = r + inp[obase + (size_t)oc * SP];
        }
    }
}

// ================= launcher =================
extern "C" void kernel_launch(void* const* d_in, const int* in_sizes, int n_in,
                              void* d_out, int out_size)
{
    (void)in_sizes; (void)n_in; (void)out_size;
    const float* inp    = (const float*)d_in[0];
    const float* w_fqkv = (const float*)d_in[2];
    const float* g1 = (const float*)d_in[3];
    const float* b1 = (const float*)d_in[4];
    const float* m1 = (const float*)d_in[5];
    const float* v1 = (const float*)d_in[6];
    const float* a1 = (const float*)d_in[7];
    const float* w_tqk  = (const float*)d_in[8];
    const float* g2 = (const float*)d_in[9];
    const float* b2 = (const float*)d_in[10];
    const float* m2 = (const float*)d_in[11];
    const float* v2 = (const float*)d_in[12];
    const float* a2 = (const float*)d_in[13];
    const float* w_proj = (const float*)d_in[14];
    const float* g3 = (const float*)d_in[15];
    const float* b3 = (const float*)d_in[16];
    const float* m3 = (const float*)d_in[17];
    const float* v3 = (const float*)d_in[18];
    const float* a3 = (const float*)d_in[19];
    float* out = (float*)d_out;

    cudaFuncSetAttribute(asa_time_attn_kernel,
                         cudaFuncAttributeMaxDynamicSharedMemorySize, TQ_SMEM);

    asa_prep_kernel<<<3, 256>>>(w_fqkv, w_tqk, g1, b1, m1, v1, a1,
                                g2, b2, m2, v2, a2);
    asa_conv_mma_kernel<<<dim3(1600, BB), 320>>>(inp);
    asa_transpose_qkv_kernel<<<dim3(13, 8, BB * 48), dim3(32, 8)>>>();
    asa_freq_attn_kernel<<<dim3(TT, BB), 128>>>();
    asa_transpose_fout_kernel<<<dim3(8, 13, BB * 16), dim3(32, 8)>>>();
    asa_time_attn_kernel<<<dim3(FF, BB), 256, TQ_SMEM>>>(inp, w_proj,
        g3, b3, m3, v3, a3, out);
}